// round 1
// baseline (speedup 1.0000x reference)
#include <cuda_runtime.h>
#include <math.h>

#define TT 256
#define HH 512
#define EPSV 1e-5f

// ---------------- scratch (device globals; no allocs allowed) ----------------
__device__ __align__(16) float g_Z [TT*HH];
__device__ __align__(16) float g_Y [TT*HH];
__device__ __align__(16) float g_D [TT*HH];
__device__ __align__(16) float g_HZ[TT*HH];
__device__ __align__(16) float g_P [TT*HH];
__device__ __align__(16) float g_PD[TT*HH];
__device__ __align__(16) float g_BETA[TT*TT];
__device__ __align__(16) float g_PRE[TT*HH];
__device__ __align__(16) float g_c [TT];

// ---------------- block reductions (256 threads) ----------------
__device__ __forceinline__ float warpRedSum(float v) {
    #pragma unroll
    for (int o = 16; o > 0; o >>= 1) v += __shfl_xor_sync(0xffffffffu, v, o);
    return v;
}
__device__ __forceinline__ float warpRedMax(float v) {
    #pragma unroll
    for (int o = 16; o > 0; o >>= 1) v = fmaxf(v, __shfl_xor_sync(0xffffffffu, v, o));
    return v;
}
__device__ float blockRedSum(float v, float* s) {
    v = warpRedSum(v);
    int lane = threadIdx.x & 31, w = threadIdx.x >> 5;
    if (lane == 0) s[w] = v;
    __syncthreads();
    if (threadIdx.x < 32) {
        float x = (threadIdx.x < 8) ? s[threadIdx.x] : 0.f;
        x = warpRedSum(x);
        if (threadIdx.x == 0) s[8] = x;
    }
    __syncthreads();
    float r = s[8];
    __syncthreads();
    return r;
}
__device__ float blockRedMax(float v, float* s) {
    v = warpRedMax(v);
    int lane = threadIdx.x & 31, w = threadIdx.x >> 5;
    if (lane == 0) s[w] = v;
    __syncthreads();
    if (threadIdx.x < 32) {
        float x = (threadIdx.x < 8) ? s[threadIdx.x] : -INFINITY;
        x = warpRedMax(x);
        if (threadIdx.x == 0) s[8] = x;
    }
    __syncthreads();
    float r = s[8];
    __syncthreads();
    return r;
}

// ---------------- generic 64x64 tiled SGEMM ----------------
// C[M,N] = op(A[M,K] @ B) + bias[n], op optionally relu.
// BTRANS=false: B is K x N row-major. BTRANS=true: B is N x K row-major (use B^T).
template<bool BTRANS, bool RELU>
__global__ __launch_bounds__(256) void gemm64(
    const float* __restrict__ A, const float* __restrict__ B,
    const float* __restrict__ bias, float* __restrict__ C,
    int M, int N, int K)
{
    __shared__ float As[16][65];
    __shared__ __align__(16) float Bs[16][64];
    const int tid = threadIdx.x;
    const int bm = blockIdx.y * 64, bn = blockIdx.x * 64;
    const int tx = tid & 15, ty = tid >> 4;
    float acc[4][4] = {};

    for (int k0 = 0; k0 < K; k0 += 16) {
        {   // A tile 64x16, one float4 per thread, store transposed
            int r = tid >> 2, c4 = (tid & 3) << 2;
            const float4 v = *reinterpret_cast<const float4*>(&A[(size_t)(bm + r) * K + k0 + c4]);
            As[c4+0][r] = v.x; As[c4+1][r] = v.y; As[c4+2][r] = v.z; As[c4+3][r] = v.w;
        }
        if (!BTRANS) { // B tile 16x64
            int r = tid >> 4, c4 = (tid & 15) << 2;
            *reinterpret_cast<float4*>(&Bs[r][c4]) =
                *reinterpret_cast<const float4*>(&B[(size_t)(k0 + r) * N + bn + c4]);
        } else {       // B^T: rows are n, cols are k
            int r = tid >> 2, c4 = (tid & 3) << 2;
            const float4 v = *reinterpret_cast<const float4*>(&B[(size_t)(bn + r) * K + k0 + c4]);
            Bs[c4+0][r] = v.x; Bs[c4+1][r] = v.y; Bs[c4+2][r] = v.z; Bs[c4+3][r] = v.w;
        }
        __syncthreads();
        #pragma unroll
        for (int k = 0; k < 16; ++k) {
            float ra[4], rb[4];
            #pragma unroll
            for (int i = 0; i < 4; ++i) ra[i] = As[k][ty*4 + i];
            #pragma unroll
            for (int j = 0; j < 4; ++j) rb[j] = Bs[k][tx*4 + j];
            #pragma unroll
            for (int i = 0; i < 4; ++i)
                #pragma unroll
                for (int j = 0; j < 4; ++j)
                    acc[i][j] = fmaf(ra[i], rb[j], acc[i][j]);
        }
        __syncthreads();
    }
    #pragma unroll
    for (int i = 0; i < 4; ++i) {
        int row = bm + ty*4 + i;
        #pragma unroll
        for (int j = 0; j < 4; ++j) {
            int col = bn + tx*4 + j;
            float v = acc[i][j] + bias[col];
            if (RELU) v = fmaxf(v, 0.f);
            C[(size_t)row * N + col] = v;
        }
    }
}

// ---------------- per-row: layernorm fwd + softmax grad + LN backward ----------------
// Produces D (T,H), HZ = h*z (T,H), c[t] = sum_q h[t,q]
__global__ __launch_bounds__(256) void rows_d_kernel(
    const float* __restrict__ Y, const float* __restrict__ h,
    const float* __restrict__ Z, const float* __restrict__ gamma,
    const float* __restrict__ beta, const int* __restrict__ targets,
    float* __restrict__ D, float* __restrict__ HZ, float* __restrict__ cvec)
{
    __shared__ float sbuf[16];
    const int t = blockIdx.x;
    const int q0 = threadIdx.x, q1 = threadIdx.x + 256;
    const int tgt = targets[t];

    float u0 = Y[t*HH + q0], u1 = Y[t*HH + q1];
    float h0 = h[t*HH + q0], h1 = h[t*HH + q1];

    float sum_u = blockRedSum(u0 + u1, sbuf);
    float sum_h = blockRedSum(h0 + h1, sbuf);
    float m = sum_u * (1.f / HH);
    float du0 = u0 - m, du1 = u1 - m;
    float v = blockRedSum(du0*du0 + du1*du1, sbuf) * (1.f / HH);
    float rstd = rsqrtf(v + EPSV);
    float x0 = du0 * rstd, x1 = du1 * rstd;
    float g0 = gamma[q0], g1 = gamma[q1];
    float y0 = x0 * g0 + beta[q0];
    float y1 = x1 * g1 + beta[q1];

    float mx = blockRedMax(fmaxf(y0, y1), sbuf);
    float e0 = __expf(y0 - mx), e1 = __expf(y1 - mx);
    float se = blockRedSum(e0 + e1, sbuf);
    float inv_se = 1.f / se;
    float s0 = e0 * inv_se - (q0 == tgt ? 1.f : 0.f);
    float s1 = e1 * inv_se - (q1 == tgt ? 1.f : 0.f);
    float sg0 = s0 * g0, sg1 = s1 * g1;

    float msg  = blockRedSum(sg0 + sg1, sbuf) * (1.f / HH);
    float msgx = blockRedSum(sg0*x0 + sg1*x1, sbuf) * (1.f / HH);
    float d0 = rstd * (sg0 - msg - x0 * msgx);
    float d1 = rstd * (sg1 - msg - x1 * msgx);

    D[t*HH + q0] = d0;
    D[t*HH + q1] = d1;
    HZ[t*HH + q0] = h0 * Z[t*HH + q0];
    HZ[t*HH + q1] = h1 * Z[t*HH + q1];
    if (threadIdx.x == 0) cvec[t] = sum_h;
}

// ---------------- inclusive cumsum of h over t, and PD = P*D ----------------
__global__ __launch_bounds__(128) void prefix_kernel(
    const float* __restrict__ h, const float* __restrict__ D,
    float* __restrict__ P, float* __restrict__ PD)
{
    const int q = blockIdx.x * 128 + threadIdx.x;
    float acc = 0.f;
    #pragma unroll 4
    for (int t = 0; t < TT; ++t) {
        acc += h[t*HH + q];
        P[t*HH + q] = acc;
        PD[t*HH + q] = acc * D[t*HH + q];
    }
}

// ---------------- correction GEMM: dual-B, masked-A, fused epilogue ----------------
// C1 = tril_strict(BETA) @ D,  C2 = tril_strict(BETA) @ PD
// PRE = Y - P*C1 + C2
__global__ __launch_bounds__(256) void corr_kernel(
    const float* __restrict__ BETA, const float* __restrict__ D,
    const float* __restrict__ PD, const float* __restrict__ Y,
    const float* __restrict__ P, float* __restrict__ PRE)
{
    __shared__ float As[16][65];
    __shared__ __align__(16) float B1s[16][64];
    __shared__ __align__(16) float B2s[16][64];
    const int tid = threadIdx.x;
    const int bm = blockIdx.y * 64, bn = blockIdx.x * 64;
    const int tx = tid & 15, ty = tid >> 4;
    float acc1[4][4] = {}, acc2[4][4] = {};

    const int kend = (bm + 64 < TT) ? (bm + 64) : TT;  // rows t<bm+64 only use i<t
    for (int k0 = 0; k0 < kend; k0 += 16) {
        {
            int r = tid >> 2, c4 = (tid & 3) << 2;
            int trow = bm + r;
            const float4 v = *reinterpret_cast<const float4*>(&BETA[(size_t)trow * TT + k0 + c4]);
            As[c4+0][r] = (k0 + c4 + 0 < trow) ? v.x : 0.f;
            As[c4+1][r] = (k0 + c4 + 1 < trow) ? v.y : 0.f;
            As[c4+2][r] = (k0 + c4 + 2 < trow) ? v.z : 0.f;
            As[c4+3][r] = (k0 + c4 + 3 < trow) ? v.w : 0.f;
        }
        {
            int r = tid >> 4, c4 = (tid & 15) << 2;
            *reinterpret_cast<float4*>(&B1s[r][c4]) =
                *reinterpret_cast<const float4*>(&D [(size_t)(k0 + r) * HH + bn + c4]);
            *reinterpret_cast<float4*>(&B2s[r][c4]) =
                *reinterpret_cast<const float4*>(&PD[(size_t)(k0 + r) * HH + bn + c4]);
        }
        __syncthreads();
        #pragma unroll
        for (int k = 0; k < 16; ++k) {
            float ra[4], rb1[4], rb2[4];
            #pragma unroll
            for (int i = 0; i < 4; ++i) ra[i] = As[k][ty*4 + i];
            #pragma unroll
            for (int j = 0; j < 4; ++j) { rb1[j] = B1s[k][tx*4 + j]; rb2[j] = B2s[k][tx*4 + j]; }
            #pragma unroll
            for (int i = 0; i < 4; ++i)
                #pragma unroll
                for (int j = 0; j < 4; ++j) {
                    acc1[i][j] = fmaf(ra[i], rb1[j], acc1[i][j]);
                    acc2[i][j] = fmaf(ra[i], rb2[j], acc2[i][j]);
                }
        }
        __syncthreads();
    }
    #pragma unroll
    for (int i = 0; i < 4; ++i) {
        int row = bm + ty*4 + i;
        #pragma unroll
        for (int j = 0; j < 4; ++j) {
            int col = bn + tx*4 + j;
            size_t idx = (size_t)row * HH + col;
            PRE[idx] = Y[idx] - P[idx] * acc1[i][j] + acc2[i][j];
        }
    }
}

// ---------------- final layernorm -> output ----------------
__global__ __launch_bounds__(256) void ln_out_kernel(
    const float* __restrict__ PRE, const float* __restrict__ gamma,
    const float* __restrict__ beta, float* __restrict__ out)
{
    __shared__ float sbuf[16];
    const int t = blockIdx.x;
    const int q0 = threadIdx.x, q1 = threadIdx.x + 256;
    float u0 = PRE[t*HH + q0], u1 = PRE[t*HH + q1];
    float m = blockRedSum(u0 + u1, sbuf) * (1.f / HH);
    float d0 = u0 - m, d1 = u1 - m;
    float v = blockRedSum(d0*d0 + d1*d1, sbuf) * (1.f / HH);
    float rstd = rsqrtf(v + EPSV);
    out[t*HH + q0] = d0 * rstd * gamma[q0] + beta[q0];
    out[t*HH + q1] = d1 * rstd * gamma[q1] + beta[q1];
}

// ---------------- launch ----------------
extern "C" void kernel_launch(void* const* d_in, const int* in_sizes, int n_in,
                              void* d_out, int out_size)
{
    const float* h     = (const float*)d_in[0];
    const float* U     = (const float*)d_in[1];
    const float* W     = (const float*)d_in[2];
    const float* a     = (const float*)d_in[3];
    const float* b     = (const float*)d_in[4];
    const float* gamma = (const float*)d_in[5];
    const float* beta  = (const float*)d_in[6];
    const int*   tgts  = (const int*)d_in[7];
    float* out = (float*)d_out;

    float *Z, *Y, *D, *HZ, *P, *PD, *BETA, *PRE, *cvec;
    cudaGetSymbolAddress((void**)&Z,    g_Z);
    cudaGetSymbolAddress((void**)&Y,    g_Y);
    cudaGetSymbolAddress((void**)&D,    g_D);
    cudaGetSymbolAddress((void**)&HZ,   g_HZ);
    cudaGetSymbolAddress((void**)&P,    g_P);
    cudaGetSymbolAddress((void**)&PD,   g_PD);
    cudaGetSymbolAddress((void**)&BETA, g_BETA);
    cudaGetSymbolAddress((void**)&PRE,  g_PRE);
    cudaGetSymbolAddress((void**)&cvec, g_c);

    // 1. Z = relu(h @ U + a)                       (256x512x512)
    gemm64<false, true ><<<dim3(HH/64, TT/64), 256>>>(h, U, a, Z, TT, HH, HH);
    // 2. Y = Z @ W + b                             (256x512x512)
    gemm64<false, false><<<dim3(HH/64, TT/64), 256>>>(Z, W, b, Y, TT, HH, HH);
    // 3. per-row d, hz, c
    rows_d_kernel<<<TT, 256>>>(Y, h, Z, gamma, beta, tgts, D, HZ, cvec);
    // 4. BETA = Z @ HZ^T + c[i]                    (256x256x512)
    gemm64<true,  false><<<dim3(TT/64, TT/64), 256>>>(Z, HZ, cvec, BETA, TT, TT, HH);
    // 5. P = cumsum_t(h), PD = P*D
    prefix_kernel<<<4, 128>>>(h, D, P, PD);
    // 6. PRE = Y - P*(trilB@D) + (trilB@PD)        (256x512x256, masked)
    corr_kernel<<<dim3(HH/64, TT/64), 256>>>(BETA, D, PD, Y, P, PRE);
    // 7. out = LN(PRE)*gamma + beta
    ln_out_kernel<<<TT, 256>>>(PRE, gamma, beta, out);
}

// round 2
// speedup vs baseline: 2.3328x; 2.3328x over previous
#include <cuda_runtime.h>
#include <math.h>

#define TT 256
#define HH 512
#define SS (TT*HH)
#define EPSV 1e-5f

// ---------------- scratch (device globals; no allocs allowed) ----------------
__device__ __align__(16) float g_Z [SS];
__device__ __align__(16) float g_Y [SS];
__device__ __align__(16) float g_D [SS];
__device__ __align__(16) float g_HZ[SS];
__device__ __align__(16) float g_P [SS];
__device__ __align__(16) float g_PD[SS];
__device__ __align__(16) float g_BETA[TT*TT];
__device__ __align__(16) float g_part[4*SS];   // split-K partials (2 MB)
__device__ __align__(16) float g_c [TT];

// ---------------- f32x2 packed FMA helpers ----------------
typedef unsigned long long u64;
__device__ __forceinline__ void ffma2(u64 &d, u64 a, u64 b) {
    asm("fma.rn.f32x2 %0, %1, %2, %3;" : "=l"(d) : "l"(a), "l"(b), "l"(d));
}
__device__ __forceinline__ u64 dup2(float x) {
    u64 r; asm("mov.b64 %0, {%1, %1};" : "=l"(r) : "f"(x)); return r;
}
__device__ __forceinline__ float2 unpk(u64 v) {
    float2 r; asm("mov.b64 {%0, %1}, %2;" : "=f"(r.x), "=f"(r.y) : "l"(v)); return r;
}

// ---------------- block reductions (256 threads) ----------------
__device__ __forceinline__ float warpRedSum(float v) {
    #pragma unroll
    for (int o = 16; o > 0; o >>= 1) v += __shfl_xor_sync(0xffffffffu, v, o);
    return v;
}
__device__ __forceinline__ float warpRedMax(float v) {
    #pragma unroll
    for (int o = 16; o > 0; o >>= 1) v = fmaxf(v, __shfl_xor_sync(0xffffffffu, v, o));
    return v;
}
__device__ float blockRedSum(float v, float* s) {
    v = warpRedSum(v);
    int lane = threadIdx.x & 31, w = threadIdx.x >> 5;
    if (lane == 0) s[w] = v;
    __syncthreads();
    if (threadIdx.x < 32) {
        float x = (threadIdx.x < 8) ? s[threadIdx.x] : 0.f;
        x = warpRedSum(x);
        if (threadIdx.x == 0) s[8] = x;
    }
    __syncthreads();
    float r = s[8];
    __syncthreads();
    return r;
}
__device__ float blockRedMax(float v, float* s) {
    v = warpRedMax(v);
    int lane = threadIdx.x & 31, w = threadIdx.x >> 5;
    if (lane == 0) s[w] = v;
    __syncthreads();
    if (threadIdx.x < 32) {
        float x = (threadIdx.x < 8) ? s[threadIdx.x] : -INFINITY;
        x = warpRedMax(x);
        if (threadIdx.x == 0) s[8] = x;
    }
    __syncthreads();
    float r = s[8];
    __syncthreads();
    return r;
}

// ---------------- split-K 64x64 SGEMM with f32x2 FMA ----------------
// Partial: Cp[s][M,N] = A[:, sKc:(s+1)Kc] @ chunk of B. Slice stride = SS.
// BTRANS=false: B is Ktot x N. BTRANS=true: B is N x Ktot (use B^T).
template<bool BTRANS>
__global__ __launch_bounds__(256) void gemm_sk(
    const float* __restrict__ A, const float* __restrict__ B,
    float* __restrict__ Cp, int M, int N, int Ktot, int Kc)
{
    __shared__ __align__(16) float As[16][68];
    __shared__ __align__(16) float Bs[16][64];
    const int tid = threadIdx.x;
    const int bm = blockIdx.y * 64, bn = blockIdx.x * 64;
    const int kbase = blockIdx.z * Kc;
    const int tx = tid & 15, ty = tid >> 4;
    u64 acc[4][2] = {};

    for (int k0 = 0; k0 < Kc; k0 += 16) {
        {   // A tile 64x16, transposed store
            int r = tid >> 2, c4 = (tid & 3) << 2;
            const float4 v = *reinterpret_cast<const float4*>(
                &A[(size_t)(bm + r) * Ktot + kbase + k0 + c4]);
            As[c4+0][r] = v.x; As[c4+1][r] = v.y; As[c4+2][r] = v.z; As[c4+3][r] = v.w;
        }
        if (!BTRANS) {
            int r = tid >> 4, c4 = (tid & 15) << 2;
            *reinterpret_cast<float4*>(&Bs[r][c4]) =
                *reinterpret_cast<const float4*>(&B[(size_t)(kbase + k0 + r) * N + bn + c4]);
        } else {
            int r = tid >> 2, c4 = (tid & 3) << 2;
            const float4 v = *reinterpret_cast<const float4*>(
                &B[(size_t)(bn + r) * Ktot + kbase + k0 + c4]);
            Bs[c4+0][r] = v.x; Bs[c4+1][r] = v.y; Bs[c4+2][r] = v.z; Bs[c4+3][r] = v.w;
        }
        __syncthreads();
        #pragma unroll
        for (int k = 0; k < 16; ++k) {
            const float4 ra = *reinterpret_cast<const float4*>(&As[k][ty*4]);
            const u64* b64 = reinterpret_cast<const u64*>(&Bs[k][tx*4]);
            u64 rb0 = b64[0], rb1 = b64[1];
            u64 a0 = dup2(ra.x), a1 = dup2(ra.y), a2 = dup2(ra.z), a3 = dup2(ra.w);
            ffma2(acc[0][0], a0, rb0); ffma2(acc[0][1], a0, rb1);
            ffma2(acc[1][0], a1, rb0); ffma2(acc[1][1], a1, rb1);
            ffma2(acc[2][0], a2, rb0); ffma2(acc[2][1], a2, rb1);
            ffma2(acc[3][0], a3, rb0); ffma2(acc[3][1], a3, rb1);
        }
        __syncthreads();
    }
    float* C = Cp + (size_t)blockIdx.z * SS;
    #pragma unroll
    for (int i = 0; i < 4; ++i) {
        int row = bm + ty*4 + i;
        float2 v0 = unpk(acc[i][0]), v1 = unpk(acc[i][1]);
        float4 w = make_float4(v0.x, v0.y, v1.x, v1.y);
        *reinterpret_cast<float4*>(&C[(size_t)row * N + bn + tx*4]) = w;
    }
}

// ---------------- 4-slice reduce + bias (+relu) ----------------
template<bool RELU>
__global__ __launch_bounds__(256) void reduce4(
    const float* __restrict__ Cp, const float* __restrict__ bias,
    float* __restrict__ C, int N, int total)
{
    int i4 = (blockIdx.x * 256 + threadIdx.x) * 4;
    if (i4 >= total) return;
    float4 v0 = *reinterpret_cast<const float4*>(&Cp[i4]);
    float4 v1 = *reinterpret_cast<const float4*>(&Cp[SS + i4]);
    float4 v2 = *reinterpret_cast<const float4*>(&Cp[2*SS + i4]);
    float4 v3 = *reinterpret_cast<const float4*>(&Cp[3*SS + i4]);
    int col = i4 % N;
    float4 bb = *reinterpret_cast<const float4*>(&bias[col]);
    float4 r;
    r.x = v0.x + v1.x + v2.x + v3.x + bb.x;
    r.y = v0.y + v1.y + v2.y + v3.y + bb.y;
    r.z = v0.z + v1.z + v2.z + v3.z + bb.z;
    r.w = v0.w + v1.w + v2.w + v3.w + bb.w;
    if (RELU) {
        r.x = fmaxf(r.x, 0.f); r.y = fmaxf(r.y, 0.f);
        r.z = fmaxf(r.z, 0.f); r.w = fmaxf(r.w, 0.f);
    }
    *reinterpret_cast<float4*>(&C[i4]) = r;
}

// ---------------- per-row: LN fwd + softmax grad + LN backward ----------------
__global__ __launch_bounds__(256) void rows_d_kernel(
    const float* __restrict__ Y, const float* __restrict__ h,
    const float* __restrict__ Z, const float* __restrict__ gamma,
    const float* __restrict__ beta, const int* __restrict__ targets,
    float* __restrict__ D, float* __restrict__ HZ, float* __restrict__ cvec)
{
    __shared__ float sbuf[16];
    const int t = blockIdx.x;
    const int q0 = threadIdx.x, q1 = threadIdx.x + 256;
    const int tgt = targets[t];

    float u0 = Y[t*HH + q0], u1 = Y[t*HH + q1];
    float h0 = h[t*HH + q0], h1 = h[t*HH + q1];

    float sum_u = blockRedSum(u0 + u1, sbuf);
    float sum_h = blockRedSum(h0 + h1, sbuf);
    float m = sum_u * (1.f / HH);
    float du0 = u0 - m, du1 = u1 - m;
    float v = blockRedSum(du0*du0 + du1*du1, sbuf) * (1.f / HH);
    float rstd = rsqrtf(v + EPSV);
    float x0 = du0 * rstd, x1 = du1 * rstd;
    float g0 = gamma[q0], g1 = gamma[q1];
    float y0 = x0 * g0 + beta[q0];
    float y1 = x1 * g1 + beta[q1];

    float mx = blockRedMax(fmaxf(y0, y1), sbuf);
    float e0 = __expf(y0 - mx), e1 = __expf(y1 - mx);
    float se = blockRedSum(e0 + e1, sbuf);
    float inv_se = 1.f / se;
    float s0 = e0 * inv_se - (q0 == tgt ? 1.f : 0.f);
    float s1 = e1 * inv_se - (q1 == tgt ? 1.f : 0.f);
    float sg0 = s0 * g0, sg1 = s1 * g1;

    float msg  = blockRedSum(sg0 + sg1, sbuf) * (1.f / HH);
    float msgx = blockRedSum(sg0*x0 + sg1*x1, sbuf) * (1.f / HH);
    float d0 = rstd * (sg0 - msg - x0 * msgx);
    float d1 = rstd * (sg1 - msg - x1 * msgx);

    D[t*HH + q0] = d0;
    D[t*HH + q1] = d1;
    HZ[t*HH + q0] = h0 * Z[t*HH + q0];
    HZ[t*HH + q1] = h1 * Z[t*HH + q1];
    if (threadIdx.x == 0) cvec[t] = sum_h;
}

// ---------------- inclusive cumsum of h over t, and PD = P*D ----------------
__global__ __launch_bounds__(64) void prefix_kernel(
    const float* __restrict__ h, const float* __restrict__ D,
    float* __restrict__ P, float* __restrict__ PD)
{
    const int q = blockIdx.x * 64 + threadIdx.x;
    float acc = 0.f;
    #pragma unroll 8
    for (int t = 0; t < TT; ++t) {
        acc += h[t*HH + q];
        P[t*HH + q] = acc;
        PD[t*HH + q] = acc * D[t*HH + q];
    }
}

// ---------------- correction GEMM: split-K=2, dual-B, masked-A ----------------
// C1p[s] = tril_strict(BETA)[:, chunk_s] @ D_chunk, C2p[s] = same @ PD_chunk
__global__ __launch_bounds__(256) void corr_sk(
    const float* __restrict__ BETA, const float* __restrict__ D,
    const float* __restrict__ PD, float* __restrict__ C1p, float* __restrict__ C2p)
{
    __shared__ __align__(16) float As[16][68];
    __shared__ __align__(16) float B1s[16][64];
    __shared__ __align__(16) float B2s[16][64];
    const int tid = threadIdx.x;
    const int bm = blockIdx.y * 64, bn = blockIdx.x * 64;
    const int s = blockIdx.z;
    const int tx = tid & 15, ty = tid >> 4;
    float* O1 = C1p + (size_t)s * SS;
    float* O2 = C2p + (size_t)s * SS;

    const int k_lo = s * 128;
    const int k_hi = min(k_lo + 128, bm + 64);   // rows in tile only use i < t <= bm+63

    if (k_lo >= k_hi) {  // chunk contributes nothing: write zeros
        float4 z = make_float4(0.f, 0.f, 0.f, 0.f);
        #pragma unroll
        for (int i = 0; i < 4; ++i) {
            size_t idx = (size_t)(bm + ty*4 + i) * HH + bn + tx*4;
            *reinterpret_cast<float4*>(&O1[idx]) = z;
            *reinterpret_cast<float4*>(&O2[idx]) = z;
        }
        return;
    }

    u64 acc1[4][2] = {}, acc2[4][2] = {};
    for (int k0 = k_lo; k0 < k_hi; k0 += 16) {
        {
            int r = tid >> 2, c4 = (tid & 3) << 2;
            int trow = bm + r;
            const float4 v = *reinterpret_cast<const float4*>(&BETA[(size_t)trow * TT + k0 + c4]);
            As[c4+0][r] = (k0 + c4 + 0 < trow) ? v.x : 0.f;
            As[c4+1][r] = (k0 + c4 + 1 < trow) ? v.y : 0.f;
            As[c4+2][r] = (k0 + c4 + 2 < trow) ? v.z : 0.f;
            As[c4+3][r] = (k0 + c4 + 3 < trow) ? v.w : 0.f;
        }
        {
            int r = tid >> 4, c4 = (tid & 15) << 2;
            *reinterpret_cast<float4*>(&B1s[r][c4]) =
                *reinterpret_cast<const float4*>(&D [(size_t)(k0 + r) * HH + bn + c4]);
            *reinterpret_cast<float4*>(&B2s[r][c4]) =
                *reinterpret_cast<const float4*>(&PD[(size_t)(k0 + r) * HH + bn + c4]);
        }
        __syncthreads();
        #pragma unroll
        for (int k = 0; k < 16; ++k) {
            const float4 ra = *reinterpret_cast<const float4*>(&As[k][ty*4]);
            const u64* b1 = reinterpret_cast<const u64*>(&B1s[k][tx*4]);
            const u64* b2 = reinterpret_cast<const u64*>(&B2s[k][tx*4]);
            u64 r10 = b1[0], r11 = b1[1], r20 = b2[0], r21 = b2[1];
            u64 a0 = dup2(ra.x), a1 = dup2(ra.y), a2 = dup2(ra.z), a3 = dup2(ra.w);
            ffma2(acc1[0][0], a0, r10); ffma2(acc1[0][1], a0, r11);
            ffma2(acc2[0][0], a0, r20); ffma2(acc2[0][1], a0, r21);
            ffma2(acc1[1][0], a1, r10); ffma2(acc1[1][1], a1, r11);
            ffma2(acc2[1][0], a1, r20); ffma2(acc2[1][1], a1, r21);
            ffma2(acc1[2][0], a2, r10); ffma2(acc1[2][1], a2, r11);
            ffma2(acc2[2][0], a2, r20); ffma2(acc2[2][1], a2, r21);
            ffma2(acc1[3][0], a3, r10); ffma2(acc1[3][1], a3, r11);
            ffma2(acc2[3][0], a3, r20); ffma2(acc2[3][1], a3, r21);
        }
        __syncthreads();
    }
    #pragma unroll
    for (int i = 0; i < 4; ++i) {
        size_t idx = (size_t)(bm + ty*4 + i) * HH + bn + tx*4;
        float2 u0 = unpk(acc1[i][0]), u1 = unpk(acc1[i][1]);
        float2 w0 = unpk(acc2[i][0]), w1 = unpk(acc2[i][1]);
        *reinterpret_cast<float4*>(&O1[idx]) = make_float4(u0.x, u0.y, u1.x, u1.y);
        *reinterpret_cast<float4*>(&O2[idx]) = make_float4(w0.x, w0.y, w1.x, w1.y);
    }
}

// ---------------- fused: reduce corr partials + PRE + final layernorm ----------------
__global__ __launch_bounds__(256) void ln_fused_kernel(
    const float* __restrict__ Y, const float* __restrict__ P,
    const float* __restrict__ C1p, const float* __restrict__ C2p,
    const float* __restrict__ gamma, const float* __restrict__ beta,
    float* __restrict__ out)
{
    __shared__ float sbuf[16];
    const int t = blockIdx.x;
    const int q0 = threadIdx.x, q1 = threadIdx.x + 256;
    size_t i0 = (size_t)t*HH + q0, i1 = (size_t)t*HH + q1;

    float c1a = C1p[i0] + C1p[SS + i0];
    float c1b = C1p[i1] + C1p[SS + i1];
    float c2a = C2p[i0] + C2p[SS + i0];
    float c2b = C2p[i1] + C2p[SS + i1];
    float u0 = Y[i0] - P[i0]*c1a + c2a;
    float u1 = Y[i1] - P[i1]*c1b + c2b;

    float m = blockRedSum(u0 + u1, sbuf) * (1.f / HH);
    float d0 = u0 - m, d1 = u1 - m;
    float v = blockRedSum(d0*d0 + d1*d1, sbuf) * (1.f / HH);
    float rstd = rsqrtf(v + EPSV);
    out[i0] = d0 * rstd * gamma[q0] + beta[q0];
    out[i1] = d1 * rstd * gamma[q1] + beta[q1];
}

// ---------------- launch ----------------
extern "C" void kernel_launch(void* const* d_in, const int* in_sizes, int n_in,
                              void* d_out, int out_size)
{
    const float* h     = (const float*)d_in[0];
    const float* U     = (const float*)d_in[1];
    const float* W     = (const float*)d_in[2];
    const float* a     = (const float*)d_in[3];
    const float* b     = (const float*)d_in[4];
    const float* gamma = (const float*)d_in[5];
    const float* beta  = (const float*)d_in[6];
    const int*   tgts  = (const int*)d_in[7];
    float* out = (float*)d_out;

    float *Z, *Y, *D, *HZ, *P, *PD, *BETA, *part, *cvec;
    cudaGetSymbolAddress((void**)&Z,    g_Z);
    cudaGetSymbolAddress((void**)&Y,    g_Y);
    cudaGetSymbolAddress((void**)&D,    g_D);
    cudaGetSymbolAddress((void**)&HZ,   g_HZ);
    cudaGetSymbolAddress((void**)&P,    g_P);
    cudaGetSymbolAddress((void**)&PD,   g_PD);
    cudaGetSymbolAddress((void**)&BETA, g_BETA);
    cudaGetSymbolAddress((void**)&part, g_part);
    cudaGetSymbolAddress((void**)&cvec, g_c);

    // 1. Z = relu(h @ U + a)       split-K 4, 128 CTAs
    gemm_sk<false><<<dim3(HH/64, TT/64, 4), 256>>>(h, U, part, TT, HH, HH, 128);
    reduce4<true ><<<SS/1024, 256>>>(part, a, Z, HH, SS);
    // 2. Y = Z @ W + b
    gemm_sk<false><<<dim3(HH/64, TT/64, 4), 256>>>(Z, W, part, TT, HH, HH, 128);
    reduce4<false><<<SS/1024, 256>>>(part, b, Y, HH, SS);
    // 3. per-row d, hz, c
    rows_d_kernel<<<TT, 256>>>(Y, h, Z, gamma, beta, tgts, D, HZ, cvec);
    // 4. BETA = Z @ HZ^T + c[i]    split-K 4, 64 CTAs
    gemm_sk<true ><<<dim3(TT/64, TT/64, 4), 256>>>(Z, HZ, part, TT, TT, HH, 128);
    reduce4<false><<<(TT*TT)/1024, 256>>>(part, cvec, BETA, TT, TT*TT);
    // 5. P = cumsum_t(h), PD = P*D
    prefix_kernel<<<HH/64, 64>>>(h, D, P, PD);
    // 6. C1p/C2p partials = tril_strict(BETA) @ {D, PD}   split-K 2, 64 CTAs
    corr_sk<<<dim3(HH/64, TT/64, 2), 256>>>(BETA, D, PD, part, part + 2*SS);
    // 7. out = LN(Y - P*C1 + C2)
    ln_fused_kernel<<<TT, 256>>>(Y, P, part, part + 2*SS, gamma, beta, out);
}

// round 3
// speedup vs baseline: 2.6010x; 1.1149x over previous
#include <cuda_runtime.h>
#include <math.h>

#define TT 256
#define HH 512
#define SS (TT*HH)
#define TSQ (TT*TT)
#define EPSV 1e-5f

// ---------------- scratch (device globals; no allocs allowed) ----------------
__device__ __align__(16) float g_part[8*SS];  // staged: Zp[4SS] | Yp[4SS] -> BETAp[4SS] | C1p,C2p[4SS]
__device__ __align__(16) float g_Z [SS];
__device__ __align__(16) float g_Y [SS];
__device__ __align__(16) float g_D [SS];
__device__ __align__(16) float g_HZ[SS];
__device__ __align__(16) float g_P [SS];
__device__ __align__(16) float g_c [TT];

// ---------------- f32x2 packed FMA helpers ----------------
typedef unsigned long long u64;
__device__ __forceinline__ void ffma2(u64 &d, u64 a, u64 b) {
    asm("fma.rn.f32x2 %0, %1, %2, %3;" : "=l"(d) : "l"(a), "l"(b), "l"(d));
}
__device__ __forceinline__ u64 dup2(float x) {
    u64 r; asm("mov.b64 %0, {%1, %1};" : "=l"(r) : "f"(x)); return r;
}
__device__ __forceinline__ float2 unpk(u64 v) {
    float2 r; asm("mov.b64 {%0, %1}, %2;" : "=f"(r.x), "=f"(r.y) : "l"(v)); return r;
}

// ---------------- block reductions (256 threads) ----------------
__device__ __forceinline__ float warpRedSum(float v) {
    #pragma unroll
    for (int o = 16; o > 0; o >>= 1) v += __shfl_xor_sync(0xffffffffu, v, o);
    return v;
}
__device__ __forceinline__ float warpRedMax(float v) {
    #pragma unroll
    for (int o = 16; o > 0; o >>= 1) v = fmaxf(v, __shfl_xor_sync(0xffffffffu, v, o));
    return v;
}
__device__ float blockRedSum(float v, float* s) {
    v = warpRedSum(v);
    int lane = threadIdx.x & 31, w = threadIdx.x >> 5;
    if (lane == 0) s[w] = v;
    __syncthreads();
    if (threadIdx.x < 32) {
        float x = (threadIdx.x < 8) ? s[threadIdx.x] : 0.f;
        x = warpRedSum(x);
        if (threadIdx.x == 0) s[8] = x;
    }
    __syncthreads();
    float r = s[8];
    __syncthreads();
    return r;
}
__device__ float blockRedMax(float v, float* s) {
    v = warpRedMax(v);
    int lane = threadIdx.x & 31, w = threadIdx.x >> 5;
    if (lane == 0) s[w] = v;
    __syncthreads();
    if (threadIdx.x < 32) {
        float x = (threadIdx.x < 8) ? s[threadIdx.x] : -INFINITY;
        x = warpRedMax(x);
        if (threadIdx.x == 0) s[8] = x;
    }
    __syncthreads();
    float r = s[8];
    __syncthreads();
    return r;
}

// =================================================================
// split-K 64x64 SGEMM, f32x2 FMA, duplicated-A smem, reg prefetch.
// AFUSE: A operand = relu(sum of 4 slices of Ap (stride SS) + abias[k]).
// BTRANS: B is N x Ktot (use B^T), else Ktot x N.
// Cp slice for this z: Cp + z*csliceStride.
// =================================================================
template<bool BTRANS, bool AFUSE>
__global__ __launch_bounds__(256) void gemm_sk(
    const float* __restrict__ A, const float* __restrict__ B,
    const float* __restrict__ abias, float* __restrict__ Cp,
    int N, int Ktot, int Kc, int csliceStride)
{
    __shared__ __align__(16) u64   As2[16][65];
    __shared__ __align__(16) float Bs [16][68];
    const int tid = threadIdx.x;
    const int bm = blockIdx.y * 64, bn = blockIdx.x * 64;
    const int kbase = blockIdx.z * Kc;
    const int tx = tid & 15, ty = tid >> 4;
    const int ar = tid >> 2, ac4 = (tid & 3) << 2;   // A-loader coords
    const int br = tid >> 4, bc4 = (tid & 15) << 2;  // B-loader coords (no-trans)
    u64 acc[4][2] = {};

    const int niter = Kc >> 4;
    float4 pa, pb;

    // ---- loaders ----
    auto loadA = [&](int k0) -> float4 {
        if (AFUSE) {
            size_t off = (size_t)(bm + ar) * Ktot + kbase + k0 + ac4;
            float4 v0 = *reinterpret_cast<const float4*>(&A[off]);
            float4 v1 = *reinterpret_cast<const float4*>(&A[SS + off]);
            float4 v2 = *reinterpret_cast<const float4*>(&A[2*SS + off]);
            float4 v3 = *reinterpret_cast<const float4*>(&A[3*SS + off]);
            float4 bb = *reinterpret_cast<const float4*>(&abias[kbase + k0 + ac4]);
            float4 r;
            r.x = fmaxf(v0.x+v1.x+v2.x+v3.x+bb.x, 0.f);
            r.y = fmaxf(v0.y+v1.y+v2.y+v3.y+bb.y, 0.f);
            r.z = fmaxf(v0.z+v1.z+v2.z+v3.z+bb.z, 0.f);
            r.w = fmaxf(v0.w+v1.w+v2.w+v3.w+bb.w, 0.f);
            return r;
        } else {
            return *reinterpret_cast<const float4*>(&A[(size_t)(bm + ar) * Ktot + kbase + k0 + ac4]);
        }
    };
    auto loadB = [&](int k0) -> float4 {
        if (!BTRANS)
            return *reinterpret_cast<const float4*>(&B[(size_t)(kbase + k0 + br) * N + bn + bc4]);
        else
            return *reinterpret_cast<const float4*>(&B[(size_t)(bn + ar) * Ktot + kbase + k0 + ac4]);
    };

    pa = loadA(0); pb = loadB(0);

    for (int it = 0; it < niter; ++it) {
        // stage to smem
        As2[ac4+0][ar] = dup2(pa.x); As2[ac4+1][ar] = dup2(pa.y);
        As2[ac4+2][ar] = dup2(pa.z); As2[ac4+3][ar] = dup2(pa.w);
        if (!BTRANS) {
            *reinterpret_cast<float4*>(&Bs[br][bc4]) = pb;
        } else {
            Bs[ac4+0][ar] = pb.x; Bs[ac4+1][ar] = pb.y;
            Bs[ac4+2][ar] = pb.z; Bs[ac4+3][ar] = pb.w;
        }
        __syncthreads();
        if (it + 1 < niter) { pa = loadA((it+1) << 4); pb = loadB((it+1) << 4); }
        #pragma unroll
        for (int k = 0; k < 16; ++k) {
            const u64* ap = &As2[k][ty*4];
            u64 a0 = ap[0], a1 = ap[1], a2 = ap[2], a3 = ap[3];
            const u64* bp = reinterpret_cast<const u64*>(&Bs[k][tx*4]);
            u64 rb0 = bp[0], rb1 = bp[1];
            ffma2(acc[0][0], a0, rb0); ffma2(acc[0][1], a0, rb1);
            ffma2(acc[1][0], a1, rb0); ffma2(acc[1][1], a1, rb1);
            ffma2(acc[2][0], a2, rb0); ffma2(acc[2][1], a2, rb1);
            ffma2(acc[3][0], a3, rb0); ffma2(acc[3][1], a3, rb1);
        }
        __syncthreads();
    }
    float* C = Cp + (size_t)blockIdx.z * csliceStride;
    #pragma unroll
    for (int i = 0; i < 4; ++i) {
        int row = bm + ty*4 + i;
        float2 v0 = unpk(acc[i][0]), v1 = unpk(acc[i][1]);
        *reinterpret_cast<float4*>(&C[(size_t)row * N + bn + tx*4]) =
            make_float4(v0.x, v0.y, v1.x, v1.y);
    }
}

// =================================================================
// rows kernel (blocks 0..TT-1): fuse Z-reduce+relu, Y-reduce+bias,
// LN fwd, softmax grad, LN backward -> D, HZ, c. Writes Z, Y too.
// blocks TT..TT+1: P = inclusive cumsum_t(h) for 512 columns.
// =================================================================
__global__ __launch_bounds__(256) void rows_kernel(
    const float* __restrict__ Zp, const float* __restrict__ Yp,
    const float* __restrict__ h, const float* __restrict__ avec,
    const float* __restrict__ bvec, const float* __restrict__ gamma,
    const float* __restrict__ beta, const int* __restrict__ targets,
    float* __restrict__ Z, float* __restrict__ Y, float* __restrict__ D,
    float* __restrict__ HZ, float* __restrict__ cvec, float* __restrict__ P)
{
    if (blockIdx.x >= TT) {
        // prefix path: one column per thread
        const int q = (blockIdx.x - TT) * 256 + threadIdx.x;
        float acc = 0.f;
        #pragma unroll 8
        for (int t = 0; t < TT; ++t) {
            acc += h[t*HH + q];
            P[t*HH + q] = acc;
        }
        return;
    }

    __shared__ float sbuf[16];
    const int t = blockIdx.x;
    const int q0 = threadIdx.x, q1 = threadIdx.x + 256;
    const int tgt = targets[t];
    const size_t i0 = (size_t)t*HH + q0, i1 = (size_t)t*HH + q1;

    float z0 = fmaxf(Zp[i0] + Zp[SS+i0] + Zp[2*SS+i0] + Zp[3*SS+i0] + avec[q0], 0.f);
    float z1 = fmaxf(Zp[i1] + Zp[SS+i1] + Zp[2*SS+i1] + Zp[3*SS+i1] + avec[q1], 0.f);
    float u0 = Yp[i0] + Yp[SS+i0] + Yp[2*SS+i0] + Yp[3*SS+i0] + bvec[q0];
    float u1 = Yp[i1] + Yp[SS+i1] + Yp[2*SS+i1] + Yp[3*SS+i1] + bvec[q1];
    float h0 = h[i0], h1 = h[i1];

    Z[i0] = z0; Z[i1] = z1;
    Y[i0] = u0; Y[i1] = u1;
    HZ[i0] = h0 * z0; HZ[i1] = h1 * z1;

    float sum_u = blockRedSum(u0 + u1, sbuf);
    float sum_h = blockRedSum(h0 + h1, sbuf);
    float m = sum_u * (1.f / HH);
    float du0 = u0 - m, du1 = u1 - m;
    float v = blockRedSum(du0*du0 + du1*du1, sbuf) * (1.f / HH);
    float rstd = rsqrtf(v + EPSV);
    float x0 = du0 * rstd, x1 = du1 * rstd;
    float g0 = gamma[q0], g1 = gamma[q1];
    float y0 = x0 * g0 + beta[q0];
    float y1 = x1 * g1 + beta[q1];

    float mx = blockRedMax(fmaxf(y0, y1), sbuf);
    float e0 = __expf(y0 - mx), e1 = __expf(y1 - mx);
    float se = blockRedSum(e0 + e1, sbuf);
    float inv_se = 1.f / se;
    float s0 = e0 * inv_se - (q0 == tgt ? 1.f : 0.f);
    float s1 = e1 * inv_se - (q1 == tgt ? 1.f : 0.f);
    float sg0 = s0 * g0, sg1 = s1 * g1;

    float msg  = blockRedSum(sg0 + sg1, sbuf) * (1.f / HH);
    float msgx = blockRedSum(sg0*x0 + sg1*x1, sbuf) * (1.f / HH);
    D[i0] = rstd * (sg0 - msg - x0 * msgx);
    D[i1] = rstd * (sg1 - msg - x1 * msgx);
    if (threadIdx.x == 0) cvec[t] = sum_h;
}

// =================================================================
// corr GEMM: A = tril_strict(sum of 8 BETA slices + c[i]); dual-B
// B1 = D, B2 = P*D (built in loader). split-K 2.
// =================================================================
__global__ __launch_bounds__(256) void corr_sk(
    const float* __restrict__ Bp, const float* __restrict__ cvec,
    const float* __restrict__ D, const float* __restrict__ P,
    float* __restrict__ C1p, float* __restrict__ C2p)
{
    __shared__ __align__(16) u64   As2[16][65];
    __shared__ __align__(16) float B1s[16][68];
    __shared__ __align__(16) float B2s[16][68];
    const int tid = threadIdx.x;
    const int bm = blockIdx.y * 64, bn = blockIdx.x * 64;
    const int s = blockIdx.z;
    const int tx = tid & 15, ty = tid >> 4;
    const int ar = tid >> 2, ac4 = (tid & 3) << 2;
    const int br = tid >> 4, bc4 = (tid & 15) << 2;
    float* O1 = C1p + (size_t)s * SS;
    float* O2 = C2p + (size_t)s * SS;

    const int k_lo = s * 128;
    const int k_hi = min(k_lo + 128, bm + 64);   // rows t only need i < t

    if (k_lo >= k_hi) {
        float4 z = make_float4(0.f, 0.f, 0.f, 0.f);
        #pragma unroll
        for (int i = 0; i < 4; ++i) {
            size_t idx = (size_t)(bm + ty*4 + i) * HH + bn + tx*4;
            *reinterpret_cast<float4*>(&O1[idx]) = z;
            *reinterpret_cast<float4*>(&O2[idx]) = z;
        }
        return;
    }

    auto loadA = [&](int k0) -> float4 {
        const int trow = bm + ar;
        size_t off = (size_t)trow * TT + k0 + ac4;
        float4 r = make_float4(0.f, 0.f, 0.f, 0.f);
        #pragma unroll
        for (int sl = 0; sl < 8; ++sl) {
            float4 v = *reinterpret_cast<const float4*>(&Bp[(size_t)sl * TSQ + off]);
            r.x += v.x; r.y += v.y; r.z += v.z; r.w += v.w;
        }
        float4 cc = *reinterpret_cast<const float4*>(&cvec[k0 + ac4]);
        r.x = (k0 + ac4 + 0 < trow) ? r.x + cc.x : 0.f;
        r.y = (k0 + ac4 + 1 < trow) ? r.y + cc.y : 0.f;
        r.z = (k0 + ac4 + 2 < trow) ? r.z + cc.z : 0.f;
        r.w = (k0 + ac4 + 3 < trow) ? r.w + cc.w : 0.f;
        return r;
    };
    float4 pa = loadA(k_lo);
    float4 pd = *reinterpret_cast<const float4*>(&D[(size_t)(k_lo + br) * HH + bn + bc4]);
    float4 pp = *reinterpret_cast<const float4*>(&P[(size_t)(k_lo + br) * HH + bn + bc4]);

    u64 acc1[4][2] = {}, acc2[4][2] = {};
    for (int k0 = k_lo; k0 < k_hi; k0 += 16) {
        As2[ac4+0][ar] = dup2(pa.x); As2[ac4+1][ar] = dup2(pa.y);
        As2[ac4+2][ar] = dup2(pa.z); As2[ac4+3][ar] = dup2(pa.w);
        *reinterpret_cast<float4*>(&B1s[br][bc4]) = pd;
        *reinterpret_cast<float4*>(&B2s[br][bc4]) =
            make_float4(pd.x*pp.x, pd.y*pp.y, pd.z*pp.z, pd.w*pp.w);
        __syncthreads();
        if (k0 + 16 < k_hi) {
            pa = loadA(k0 + 16);
            pd = *reinterpret_cast<const float4*>(&D[(size_t)(k0 + 16 + br) * HH + bn + bc4]);
            pp = *reinterpret_cast<const float4*>(&P[(size_t)(k0 + 16 + br) * HH + bn + bc4]);
        }
        #pragma unroll
        for (int k = 0; k < 16; ++k) {
            const u64* ap = &As2[k][ty*4];
            u64 a0 = ap[0], a1 = ap[1], a2 = ap[2], a3 = ap[3];
            const u64* b1 = reinterpret_cast<const u64*>(&B1s[k][tx*4]);
            const u64* b2 = reinterpret_cast<const u64*>(&B2s[k][tx*4]);
            u64 r10 = b1[0], r11 = b1[1], r20 = b2[0], r21 = b2[1];
            ffma2(acc1[0][0], a0, r10); ffma2(acc1[0][1], a0, r11);
            ffma2(acc2[0][0], a0, r20); ffma2(acc2[0][1], a0, r21);
            ffma2(acc1[1][0], a1, r10); ffma2(acc1[1][1], a1, r11);
            ffma2(acc2[1][0], a1, r20); ffma2(acc2[1][1], a1, r21);
            ffma2(acc1[2][0], a2, r10); ffma2(acc1[2][1], a2, r11);
            ffma2(acc2[2][0], a2, r20); ffma2(acc2[2][1], a2, r21);
            ffma2(acc1[3][0], a3, r10); ffma2(acc1[3][1], a3, r11);
            ffma2(acc2[3][0], a3, r20); ffma2(acc2[3][1], a3, r21);
        }
        __syncthreads();
    }
    #pragma unroll
    for (int i = 0; i < 4; ++i) {
        size_t idx = (size_t)(bm + ty*4 + i) * HH + bn + tx*4;
        float2 u0 = unpk(acc1[i][0]), u1 = unpk(acc1[i][1]);
        float2 w0 = unpk(acc2[i][0]), w1 = unpk(acc2[i][1]);
        *reinterpret_cast<float4*>(&O1[idx]) = make_float4(u0.x, u0.y, u1.x, u1.y);
        *reinterpret_cast<float4*>(&O2[idx]) = make_float4(w0.x, w0.y, w1.x, w1.y);
    }
}

// ---------------- fused: reduce corr partials + PRE + final layernorm ----------------
__global__ __launch_bounds__(256) void ln_fused_kernel(
    const float* __restrict__ Y, const float* __restrict__ P,
    const float* __restrict__ C1p, const float* __restrict__ C2p,
    const float* __restrict__ gamma, const float* __restrict__ beta,
    float* __restrict__ out)
{
    __shared__ float sbuf[16];
    const int t = blockIdx.x;
    const int q0 = threadIdx.x, q1 = threadIdx.x + 256;
    size_t i0 = (size_t)t*HH + q0, i1 = (size_t)t*HH + q1;

    float c1a = C1p[i0] + C1p[SS + i0];
    float c1b = C1p[i1] + C1p[SS + i1];
    float c2a = C2p[i0] + C2p[SS + i0];
    float c2b = C2p[i1] + C2p[SS + i1];
    float u0 = Y[i0] - P[i0]*c1a + c2a;
    float u1 = Y[i1] - P[i1]*c1b + c2b;

    float m = blockRedSum(u0 + u1, sbuf) * (1.f / HH);
    float d0 = u0 - m, d1 = u1 - m;
    float v = blockRedSum(d0*d0 + d1*d1, sbuf) * (1.f / HH);
    float rstd = rsqrtf(v + EPSV);
    out[i0] = d0 * rstd * gamma[q0] + beta[q0];
    out[i1] = d1 * rstd * gamma[q1] + beta[q1];
}

// ---------------- launch ----------------
extern "C" void kernel_launch(void* const* d_in, const int* in_sizes, int n_in,
                              void* d_out, int out_size)
{
    const float* h     = (const float*)d_in[0];
    const float* U     = (const float*)d_in[1];
    const float* W     = (const float*)d_in[2];
    const float* a     = (const float*)d_in[3];
    const float* b     = (const float*)d_in[4];
    const float* gamma = (const float*)d_in[5];
    const float* beta  = (const float*)d_in[6];
    const int*   tgts  = (const int*)d_in[7];
    float* out = (float*)d_out;

    float *part, *Z, *Y, *D, *HZ, *P, *cvec;
    cudaGetSymbolAddress((void**)&part, g_part);
    cudaGetSymbolAddress((void**)&Z,    g_Z);
    cudaGetSymbolAddress((void**)&Y,    g_Y);
    cudaGetSymbolAddress((void**)&D,    g_D);
    cudaGetSymbolAddress((void**)&HZ,   g_HZ);
    cudaGetSymbolAddress((void**)&P,    g_P);
    cudaGetSymbolAddress((void**)&cvec, g_c);

    float* Zp = part;            // 4 slices of SS
    float* Yp = part + 4*SS;     // 4 slices of SS
    float* Bp = part;            // 8 slices of TT*TT (reuses Zp region)
    float* C1p = part + 4*SS;    // 2 slices of SS (reuses Yp region)
    float* C2p = part + 6*SS;    // 2 slices of SS

    // 1. Zp = split-K partials of h @ U          (128 CTAs)
    gemm_sk<false, false><<<dim3(HH/64, TT/64, 4), 256>>>(h, U, nullptr, Zp, HH, HH, 128, SS);
    // 2. Yp = split-K partials of relu(sumZp+a) @ W   (128 CTAs, fused Z reduce)
    gemm_sk<false, true ><<<dim3(HH/64, TT/64, 4), 256>>>(Zp, W, a, Yp, HH, HH, 128, SS);
    // 3. rows: Z,Y,HZ,D,c + P-prefix blocks
    rows_kernel<<<TT + 2, 256>>>(Zp, Yp, h, a, b, gamma, beta, tgts, Z, Y, D, HZ, cvec, P);
    // 4. Bp = split-K-8 partials of Z @ HZ^T     (128 CTAs)
    gemm_sk<true,  false><<<dim3(TT/64, TT/64, 8), 256>>>(Z, HZ, nullptr, Bp, TT, HH, 64, TSQ);
    // 5. corr: C1p/C2p = tril_strict(sumBp + c) @ {D, P*D}   (split-K 2, 64 CTAs)
    corr_sk<<<dim3(HH/64, TT/64, 2), 256>>>(Bp, cvec, D, P, C1p, C2p);
    // 6. out = LN(Y - P*C1 + C2)
    ln_fused_kernel<<<TT, 256>>>(Y, P, C1p, C2p, gamma, beta, out);
}

// round 4
// speedup vs baseline: 3.0689x; 1.1799x over previous
#include <cuda_runtime.h>
#include <math.h>

#define TT 256
#define HH 512
#define SS (TT*HH)
#define TSQ (TT*TT)
#define EPSV 1e-5f
#define NCTA 296

// ---------------- scratch (device globals; no allocs allowed) ----------------
__device__ __align__(16) float g_part[32*SS];  // Zp/Bp[8SS] | Yp[8SS] | C1p[8SS] | C2p[8SS]
__device__ __align__(16) float g_Z [SS];
__device__ __align__(16) float g_Y [SS];
__device__ __align__(16) float g_D [SS];
__device__ __align__(16) float g_HZ[SS];
__device__ __align__(16) float g_P [SS];
__device__ __align__(16) float g_c [TT];
__device__ unsigned g_cnt = 0;
__device__ volatile unsigned g_gen = 0;

// ---------------- f32x2 packed FMA helpers ----------------
typedef unsigned long long u64;
__device__ __forceinline__ void ffma2(u64 &d, u64 a, u64 b) {
    asm("fma.rn.f32x2 %0, %1, %2, %3;" : "=l"(d) : "l"(a), "l"(b), "l"(d));
}
__device__ __forceinline__ u64 dup2(float x) {
    u64 r; asm("mov.b64 %0, {%1, %1};" : "=l"(r) : "f"(x)); return r;
}
__device__ __forceinline__ float2 unpk(u64 v) {
    float2 r; asm("mov.b64 {%0, %1}, %2;" : "=f"(r.x), "=f"(r.y) : "l"(v)); return r;
}

// ---------------- shared memory (one block reused by all phases) ----------------
struct __align__(16) Smem {
    u64   As2[16][65];
    float B1s[16][68];
    float B2s[16][68];
    float red[16];
};

// ---------------- grid barrier (all NCTA resident) ----------------
__device__ __forceinline__ void gbar() {
    __syncthreads();
    if (threadIdx.x == 0) {
        unsigned gen = g_gen;
        __threadfence();                       // order gen-load & data stores before arrival
        if (atomicAdd(&g_cnt, 1u) == (unsigned)(gridDim.x - 1)) {
            g_cnt = 0;
            __threadfence();
            g_gen = gen + 1;
        } else {
            while (g_gen == gen) __nanosleep(64);
        }
        __threadfence();                       // acquire + L1 invalidate
    }
    __syncthreads();
}

// ---------------- block reductions (256 threads) ----------------
__device__ __forceinline__ float warpRedSum(float v) {
    #pragma unroll
    for (int o = 16; o > 0; o >>= 1) v += __shfl_xor_sync(0xffffffffu, v, o);
    return v;
}
__device__ __forceinline__ float warpRedMax(float v) {
    #pragma unroll
    for (int o = 16; o > 0; o >>= 1) v = fmaxf(v, __shfl_xor_sync(0xffffffffu, v, o));
    return v;
}
__device__ float blockRedSum(float v, float* s) {
    v = warpRedSum(v);
    int lane = threadIdx.x & 31, w = threadIdx.x >> 5;
    if (lane == 0) s[w] = v;
    __syncthreads();
    if (threadIdx.x < 32) {
        float x = (threadIdx.x < 8) ? s[threadIdx.x] : 0.f;
        x = warpRedSum(x);
        if (threadIdx.x == 0) s[8] = x;
    }
    __syncthreads();
    float r = s[8];
    __syncthreads();
    return r;
}
__device__ float blockRedMax(float v, float* s) {
    v = warpRedMax(v);
    int lane = threadIdx.x & 31, w = threadIdx.x >> 5;
    if (lane == 0) s[w] = v;
    __syncthreads();
    if (threadIdx.x < 32) {
        float x = (threadIdx.x < 8) ? s[threadIdx.x] : -INFINITY;
        x = warpRedMax(x);
        if (threadIdx.x == 0) s[8] = x;
    }
    __syncthreads();
    float r = s[8];
    __syncthreads();
    return r;
}

__device__ __forceinline__ float4 ld4(const float* p) {
    return __ldcg(reinterpret_cast<const float4*>(p));
}

// =================================================================
// 64x64 GEMM tile, f32x2 FMA, duplicated-A smem, reg prefetch.
// tile -> bn = (tile%nx)*64, bm = ((tile/nx)&3)*64, z = tile/(nx*4)
// =================================================================
template<bool BTRANS>
__device__ void gemm_tile(Smem* sm, const float* __restrict__ A,
                          const float* __restrict__ B, float* __restrict__ Cp,
                          int tile, int nx, int Kc, int N, int Ktot, int cstride)
{
    const int tid = threadIdx.x;
    const int bn = (tile % nx) * 64;
    const int bm = ((tile / nx) & 3) * 64;
    const int kbase = (tile / (nx * 4)) * Kc;
    const int tx = tid & 15, ty = tid >> 4;
    const int ar = tid >> 2, ac4 = (tid & 3) << 2;
    const int br = tid >> 4, bc4 = (tid & 15) << 2;
    u64 acc[4][2] = {};
    const int niter = Kc >> 4;

    auto loadA = [&](int k0) -> float4 {
        return ld4(&A[(size_t)(bm + ar) * Ktot + kbase + k0 + ac4]);
    };
    auto loadB = [&](int k0) -> float4 {
        if (!BTRANS) return ld4(&B[(size_t)(kbase + k0 + br) * N + bn + bc4]);
        else         return ld4(&B[(size_t)(bn + ar) * Ktot + kbase + k0 + ac4]);
    };
    float4 pa = loadA(0), pb = loadB(0);

    for (int it = 0; it < niter; ++it) {
        sm->As2[ac4+0][ar] = dup2(pa.x); sm->As2[ac4+1][ar] = dup2(pa.y);
        sm->As2[ac4+2][ar] = dup2(pa.z); sm->As2[ac4+3][ar] = dup2(pa.w);
        if (!BTRANS) {
            *reinterpret_cast<float4*>(&sm->B1s[br][bc4]) = pb;
        } else {
            sm->B1s[ac4+0][ar] = pb.x; sm->B1s[ac4+1][ar] = pb.y;
            sm->B1s[ac4+2][ar] = pb.z; sm->B1s[ac4+3][ar] = pb.w;
        }
        __syncthreads();
        if (it + 1 < niter) { pa = loadA((it+1) << 4); pb = loadB((it+1) << 4); }
        #pragma unroll
        for (int k = 0; k < 16; ++k) {
            const u64* ap = &sm->As2[k][ty*4];
            u64 a0 = ap[0], a1 = ap[1], a2 = ap[2], a3 = ap[3];
            const u64* bp = reinterpret_cast<const u64*>(&sm->B1s[k][tx*4]);
            u64 rb0 = bp[0], rb1 = bp[1];
            ffma2(acc[0][0], a0, rb0); ffma2(acc[0][1], a0, rb1);
            ffma2(acc[1][0], a1, rb0); ffma2(acc[1][1], a1, rb1);
            ffma2(acc[2][0], a2, rb0); ffma2(acc[2][1], a2, rb1);
            ffma2(acc[3][0], a3, rb0); ffma2(acc[3][1], a3, rb1);
        }
        __syncthreads();
    }
    float* C = Cp + (size_t)(tile / (nx * 4)) * cstride;
    #pragma unroll
    for (int i = 0; i < 4; ++i) {
        int row = bm + ty*4 + i;
        float2 v0 = unpk(acc[i][0]), v1 = unpk(acc[i][1]);
        *reinterpret_cast<float4*>(&C[(size_t)row * N + bn + tx*4]) =
            make_float4(v0.x, v0.y, v1.x, v1.y);
    }
}

// ---------------- phase 2a: Z = relu(sum 8 Zp + a) ----------------
__device__ void zred_tile(int tile, const float* Zp, const float* a, float* Z) {
    int i4 = tile * 1024 + threadIdx.x * 4;
    float4 r = make_float4(0.f, 0.f, 0.f, 0.f);
    #pragma unroll
    for (int s = 0; s < 8; ++s) {
        float4 v = ld4(&Zp[(size_t)s * SS + i4]);
        r.x += v.x; r.y += v.y; r.z += v.z; r.w += v.w;
    }
    float4 bb = ld4(&a[i4 & (HH - 1)]);
    r.x = fmaxf(r.x + bb.x, 0.f); r.y = fmaxf(r.y + bb.y, 0.f);
    r.z = fmaxf(r.z + bb.z, 0.f); r.w = fmaxf(r.w + bb.w, 0.f);
    *reinterpret_cast<float4*>(&Z[i4]) = r;
}

// ---------------- phase 2b: P = inclusive cumsum_t(h), segmented scan ----------------
// tile p in [0,16): 32 columns, 8 threads per column (32 t's each)
__device__ void prefix_tile(int p, const float* __restrict__ h, float* __restrict__ P) {
    const int q = p * 32 + (threadIdx.x >> 3);
    const int seg = threadIdx.x & 7;
    const int t0 = seg * 32;
    float v[32];
    #pragma unroll
    for (int i = 0; i < 32; ++i) v[i] = __ldcg(&h[(size_t)(t0 + i) * HH + q]);
    #pragma unroll
    for (int i = 1; i < 32; ++i) v[i] += v[i-1];
    float run = v[31];
    #pragma unroll
    for (int d = 1; d < 8; d <<= 1) {
        float n = __shfl_up_sync(0xffffffffu, run, d);
        if (seg >= d) run += n;
    }
    float off = run - v[31];
    #pragma unroll
    for (int i = 0; i < 32; ++i) P[(size_t)(t0 + i) * HH + q] = v[i] + off;
}

// ---------------- phase 4: rows (Y reduce, LN fwd, softmax grad, LN bwd) ----------------
__device__ void rows_tile(Smem* sm, int t,
    const float* __restrict__ Yp, const float* __restrict__ h,
    const float* __restrict__ bvec, const float* __restrict__ gamma,
    const float* __restrict__ beta, const int* __restrict__ targets,
    const float* __restrict__ Z, float* __restrict__ Y, float* __restrict__ D,
    float* __restrict__ HZ, float* __restrict__ cvec)
{
    const int q0 = threadIdx.x, q1 = threadIdx.x + 256;
    const int tgt = targets[t];
    const size_t i0 = (size_t)t*HH + q0, i1 = (size_t)t*HH + q1;

    float u0 = bvec[q0], u1 = bvec[q1];
    #pragma unroll
    for (int s = 0; s < 8; ++s) {
        u0 += __ldcg(&Yp[(size_t)s*SS + i0]);
        u1 += __ldcg(&Yp[(size_t)s*SS + i1]);
    }
    float h0 = h[i0], h1 = h[i1];
    float z0 = __ldcg(&Z[i0]), z1 = __ldcg(&Z[i1]);

    Y[i0] = u0; Y[i1] = u1;
    HZ[i0] = h0 * z0; HZ[i1] = h1 * z1;

    float sum_u = blockRedSum(u0 + u1, sm->red);
    float sum_h = blockRedSum(h0 + h1, sm->red);
    float m = sum_u * (1.f / HH);
    float du0 = u0 - m, du1 = u1 - m;
    float v = blockRedSum(du0*du0 + du1*du1, sm->red) * (1.f / HH);
    float rstd = rsqrtf(v + EPSV);
    float x0 = du0 * rstd, x1 = du1 * rstd;
    float g0 = gamma[q0], g1 = gamma[q1];
    float y0 = x0 * g0 + beta[q0];
    float y1 = x1 * g1 + beta[q1];

    float mx = blockRedMax(fmaxf(y0, y1), sm->red);
    float e0 = __expf(y0 - mx), e1 = __expf(y1 - mx);
    float se = blockRedSum(e0 + e1, sm->red);
    float inv_se = 1.f / se;
    float s0 = e0 * inv_se - (q0 == tgt ? 1.f : 0.f);
    float s1 = e1 * inv_se - (q1 == tgt ? 1.f : 0.f);
    float sg0 = s0 * g0, sg1 = s1 * g1;

    float msg  = blockRedSum(sg0 + sg1, sm->red) * (1.f / HH);
    float msgx = blockRedSum(sg0*x0 + sg1*x1, sm->red) * (1.f / HH);
    D[i0] = rstd * (sg0 - msg - x0 * msgx);
    D[i1] = rstd * (sg1 - msg - x1 * msgx);
    if (threadIdx.x == 0) cvec[t] = sum_h;
}

// ---------------- phase 6: corr GEMM tile (split-K 8, Kc=32) ----------------
// A = tril_strict(sum 16 Bp slices + c[i]); B1 = D, B2 = P*D
__device__ void corr_tile(Smem* sm, int tile,
    const float* __restrict__ Bp, const float* __restrict__ cvec,
    const float* __restrict__ D, const float* __restrict__ P,
    float* __restrict__ C1p, float* __restrict__ C2p)
{
    const int tid = threadIdx.x;
    const int bn = (tile & 7) * 64;
    const int bm = ((tile >> 3) & 3) * 64;
    const int z  = tile >> 5;
    const int tx = tid & 15, ty = tid >> 4;
    const int ar = tid >> 2, ac4 = (tid & 3) << 2;
    const int br = tid >> 4, bc4 = (tid & 15) << 2;
    float* O1 = C1p + (size_t)z * SS;
    float* O2 = C2p + (size_t)z * SS;

    const int k_lo = z * 32;
    const int k_hi = min(k_lo + 32, bm + 64);

    if (k_lo >= k_hi) {
        float4 zz = make_float4(0.f, 0.f, 0.f, 0.f);
        #pragma unroll
        for (int i = 0; i < 4; ++i) {
            size_t idx = (size_t)(bm + ty*4 + i) * HH + bn + tx*4;
            *reinterpret_cast<float4*>(&O1[idx]) = zz;
            *reinterpret_cast<float4*>(&O2[idx]) = zz;
        }
        return;
    }

    auto loadA = [&](int k0) -> float4 {
        const int trow = bm + ar;
        size_t off = (size_t)trow * TT + k0 + ac4;
        float4 r = make_float4(0.f, 0.f, 0.f, 0.f);
        #pragma unroll
        for (int sl = 0; sl < 16; ++sl) {
            float4 v = ld4(&Bp[(size_t)sl * TSQ + off]);
            r.x += v.x; r.y += v.y; r.z += v.z; r.w += v.w;
        }
        float4 cc = ld4(&cvec[k0 + ac4]);
        r.x = (k0 + ac4 + 0 < trow) ? r.x + cc.x : 0.f;
        r.y = (k0 + ac4 + 1 < trow) ? r.y + cc.y : 0.f;
        r.z = (k0 + ac4 + 2 < trow) ? r.z + cc.z : 0.f;
        r.w = (k0 + ac4 + 3 < trow) ? r.w + cc.w : 0.f;
        return r;
    };
    float4 pa = loadA(k_lo);
    float4 pd = ld4(&D[(size_t)(k_lo + br) * HH + bn + bc4]);
    float4 pp = ld4(&P[(size_t)(k_lo + br) * HH + bn + bc4]);

    u64 acc1[4][2] = {}, acc2[4][2] = {};
    for (int k0 = k_lo; k0 < k_hi; k0 += 16) {
        sm->As2[ac4+0][ar] = dup2(pa.x); sm->As2[ac4+1][ar] = dup2(pa.y);
        sm->As2[ac4+2][ar] = dup2(pa.z); sm->As2[ac4+3][ar] = dup2(pa.w);
        *reinterpret_cast<float4*>(&sm->B1s[br][bc4]) = pd;
        *reinterpret_cast<float4*>(&sm->B2s[br][bc4]) =
            make_float4(pd.x*pp.x, pd.y*pp.y, pd.z*pp.z, pd.w*pp.w);
        __syncthreads();
        if (k0 + 16 < k_hi) {
            pa = loadA(k0 + 16);
            pd = ld4(&D[(size_t)(k0 + 16 + br) * HH + bn + bc4]);
            pp = ld4(&P[(size_t)(k0 + 16 + br) * HH + bn + bc4]);
        }
        #pragma unroll
        for (int k = 0; k < 16; ++k) {
            const u64* ap = &sm->As2[k][ty*4];
            u64 a0 = ap[0], a1 = ap[1], a2 = ap[2], a3 = ap[3];
            const u64* b1 = reinterpret_cast<const u64*>(&sm->B1s[k][tx*4]);
            const u64* b2 = reinterpret_cast<const u64*>(&sm->B2s[k][tx*4]);
            u64 r10 = b1[0], r11 = b1[1], r20 = b2[0], r21 = b2[1];
            ffma2(acc1[0][0], a0, r10); ffma2(acc1[0][1], a0, r11);
            ffma2(acc2[0][0], a0, r20); ffma2(acc2[0][1], a0, r21);
            ffma2(acc1[1][0], a1, r10); ffma2(acc1[1][1], a1, r11);
            ffma2(acc2[1][0], a1, r20); ffma2(acc2[1][1], a1, r21);
            ffma2(acc1[2][0], a2, r10); ffma2(acc1[2][1], a2, r11);
            ffma2(acc2[2][0], a2, r20); ffma2(acc2[2][1], a2, r21);
            ffma2(acc1[3][0], a3, r10); ffma2(acc1[3][1], a3, r11);
            ffma2(acc2[3][0], a3, r20); ffma2(acc2[3][1], a3, r21);
        }
        __syncthreads();
    }
    #pragma unroll
    for (int i = 0; i < 4; ++i) {
        size_t idx = (size_t)(bm + ty*4 + i) * HH + bn + tx*4;
        float2 u0 = unpk(acc1[i][0]), u1 = unpk(acc1[i][1]);
        float2 w0 = unpk(acc2[i][0]), w1 = unpk(acc2[i][1]);
        *reinterpret_cast<float4*>(&O1[idx]) = make_float4(u0.x, u0.y, u1.x, u1.y);
        *reinterpret_cast<float4*>(&O2[idx]) = make_float4(w0.x, w0.y, w1.x, w1.y);
    }
}

// ---------------- phase 7: reduce corr partials + PRE + final LN ----------------
__device__ void ln_tile(Smem* sm, int t,
    const float* __restrict__ Y, const float* __restrict__ P,
    const float* __restrict__ C1p, const float* __restrict__ C2p,
    const float* __restrict__ gamma, const float* __restrict__ beta,
    float* __restrict__ out)
{
    const int q0 = threadIdx.x, q1 = threadIdx.x + 256;
    size_t i0 = (size_t)t*HH + q0, i1 = (size_t)t*HH + q1;

    float c1a = 0.f, c1b = 0.f, c2a = 0.f, c2b = 0.f;
    #pragma unroll
    for (int s = 0; s < 8; ++s) {
        c1a += __ldcg(&C1p[(size_t)s*SS + i0]);
        c1b += __ldcg(&C1p[(size_t)s*SS + i1]);
        c2a += __ldcg(&C2p[(size_t)s*SS + i0]);
        c2b += __ldcg(&C2p[(size_t)s*SS + i1]);
    }
    float u0 = __ldcg(&Y[i0]) - __ldcg(&P[i0]) * c1a + c2a;
    float u1 = __ldcg(&Y[i1]) - __ldcg(&P[i1]) * c1b + c2b;

    float m = blockRedSum(u0 + u1, sm->red) * (1.f / HH);
    float d0 = u0 - m, d1 = u1 - m;
    float v = blockRedSum(d0*d0 + d1*d1, sm->red) * (1.f / HH);
    float rstd = rsqrtf(v + EPSV);
    out[i0] = d0 * rstd * gamma[q0] + beta[q0];
    out[i1] = d1 * rstd * gamma[q1] + beta[q1];
}

// =================================================================
// mega kernel: 7 phases, 6 grid barriers, 296 persistent CTAs
// =================================================================
__global__ __launch_bounds__(256, 2) void mega_kernel(
    const float* __restrict__ h, const float* __restrict__ U,
    const float* __restrict__ W, const float* __restrict__ a,
    const float* __restrict__ b, const float* __restrict__ gamma,
    const float* __restrict__ beta, const int* __restrict__ tgts,
    float* __restrict__ out)
{
    __shared__ Smem sm;
    float* Zp  = g_part;                 // 8 slices SS (phase 1)
    float* Yp  = g_part + 8*(size_t)SS;  // 8 slices SS (phase 3)
    float* Bp  = g_part;                 // 16 slices TSQ (phase 5, reuses Zp)
    float* C1p = g_part + 16*(size_t)SS; // 8 slices SS
    float* C2p = g_part + 24*(size_t)SS; // 8 slices SS

    // Phase 1: Zp partials = h @ U   (split-K 8, Kc=64, 256 tiles)
    for (int tile = blockIdx.x; tile < 256; tile += gridDim.x)
        gemm_tile<false>(&sm, h, U, Zp, tile, 8, 64, HH, HH, SS);
    gbar();
    // Phase 2: Z = relu(sum Zp + a); P = cumsum(h)
    for (int tile = blockIdx.x; tile < 144; tile += gridDim.x) {
        if (tile < 128) zred_tile(tile, Zp, a, g_Z);
        else            prefix_tile(tile - 128, h, g_P);
    }
    gbar();
    // Phase 3: Yp partials = Z @ W   (split-K 8, 256 tiles)
    for (int tile = blockIdx.x; tile < 256; tile += gridDim.x)
        gemm_tile<false>(&sm, g_Z, W, Yp, tile, 8, 64, HH, HH, SS);
    gbar();
    // Phase 4: rows -> Y, D, HZ, c
    for (int t = blockIdx.x; t < TT; t += gridDim.x)
        rows_tile(&sm, t, Yp, h, b, gamma, beta, tgts, g_Z, g_Y, g_D, g_HZ, g_c);
    gbar();
    // Phase 5: Bp partials = Z @ HZ^T (split-K 16, Kc=32, 256 tiles)
    for (int tile = blockIdx.x; tile < 256; tile += gridDim.x)
        gemm_tile<true>(&sm, g_Z, g_HZ, Bp, tile, 4, 32, TT, HH, TSQ);
    gbar();
    // Phase 6: C1p/C2p partials = tril_strict(sum Bp + c) @ {D, P*D} (split-K 8)
    for (int tile = blockIdx.x; tile < 256; tile += gridDim.x)
        corr_tile(&sm, tile, Bp, g_c, g_D, g_P, C1p, C2p);
    gbar();
    // Phase 7: out = LN(Y - P*C1 + C2)
    for (int t = blockIdx.x; t < TT; t += gridDim.x)
        ln_tile(&sm, t, g_Y, g_P, C1p, C2p, gamma, beta, out);
}

// ---------------- launch ----------------
extern "C" void kernel_launch(void* const* d_in, const int* in_sizes, int n_in,
                              void* d_out, int out_size)
{
    const float* h     = (const float*)d_in[0];
    const float* U     = (const float*)d_in[1];
    const float* W     = (const float*)d_in[2];
    const float* a     = (const float*)d_in[3];
    const float* b     = (const float*)d_in[4];
    const float* gamma = (const float*)d_in[5];
    const float* beta  = (const float*)d_in[6];
    const int*   tgts  = (const int*)d_in[7];
    float* out = (float*)d_out;

    mega_kernel<<<NCTA, 256>>>(h, U, W, a, b, gamma, beta, tgts, out);
}

// round 6
// speedup vs baseline: 3.5475x; 1.1560x over previous
#include <cuda_runtime.h>
#include <math.h>

#define TT 256
#define HH 512
#define SS (TT*HH)
#define TSQ (TT*TT)
#define EPSV 1e-5f
#define NCTA 296

// ---------------- scratch (device globals; no allocs allowed) ----------------
__device__ __align__(16) float g_part[32*SS];  // Zp/Bp[8SS] | Yp[8SS] | C1p[8SS] | C2p[8SS]
__device__ __align__(16) float g_Z [SS];
__device__ __align__(16) float g_Y [SS];
__device__ __align__(16) float g_D [SS];
__device__ __align__(16) float g_HZ[SS];
__device__ __align__(16) float g_P [SS];
__device__ __align__(16) float g_c [TT];
__device__ unsigned g_cnt = 0;
__device__ unsigned g_gen = 0;

// ---------------- f32x2 packed FMA helpers ----------------
typedef unsigned long long u64;
__device__ __forceinline__ void ffma2(u64 &d, u64 a, u64 b) {
    asm("fma.rn.f32x2 %0, %1, %2, %3;" : "=l"(d) : "l"(a), "l"(b), "l"(d));
}
__device__ __forceinline__ u64 dup2(float x) {
    u64 r; asm("mov.b64 %0, {%1, %1};" : "=l"(r) : "f"(x)); return r;
}
__device__ __forceinline__ float2 unpk(u64 v) {
    float2 r; asm("mov.b64 {%0, %1}, %2;" : "=f"(r.x), "=f"(r.y) : "l"(v)); return r;
}

// ---------------- shared memory (reused by all phases; double-buffered) ----------------
struct __align__(16) Smem {
    float A [2][16][68];
    float B1[2][16][68];
    float B2[2][16][68];   // corr only
    float red[16];
};

// ---------------- grid barrier: release/acquire, no full fence ----------------
__device__ __forceinline__ void gbar() {
    __syncthreads();
    if (threadIdx.x == 0) {
        unsigned gen = g_gen;   // stable: can only change after ALL arrive
        unsigned old;
        asm volatile("atom.add.release.gpu.u32 %0, [%1], 1;"
                     : "=r"(old) : "l"(&g_cnt) : "memory");
        if (old == NCTA - 1) {
            g_cnt = 0;          // ordered before gen store by release below
            asm volatile("st.release.gpu.u32 [%0], %1;"
                         :: "l"(&g_gen), "r"(gen + 1) : "memory");
        } else {
            unsigned cur;
            do {
                __nanosleep(32);
                asm volatile("ld.acquire.gpu.u32 %0, [%1];"
                             : "=r"(cur) : "l"(&g_gen) : "memory");
            } while (cur == gen);
        }
    }
    __syncthreads();
}

// ---------------- block reductions (256 threads) ----------------
__device__ __forceinline__ float warpRedSum(float v) {
    #pragma unroll
    for (int o = 16; o > 0; o >>= 1) v += __shfl_xor_sync(0xffffffffu, v, o);
    return v;
}
__device__ __forceinline__ float warpRedMax(float v) {
    #pragma unroll
    for (int o = 16; o > 0; o >>= 1) v = fmaxf(v, __shfl_xor_sync(0xffffffffu, v, o));
    return v;
}
__device__ float blockRedSum(float v, float* s) {
    v = warpRedSum(v);
    int lane = threadIdx.x & 31, w = threadIdx.x >> 5;
    if (lane == 0) s[w] = v;
    __syncthreads();
    if (threadIdx.x < 32) {
        float x = (threadIdx.x < 8) ? s[threadIdx.x] : 0.f;
        x = warpRedSum(x);
        if (threadIdx.x == 0) s[8] = x;
    }
    __syncthreads();
    float r = s[8];
    __syncthreads();
    return r;
}
__device__ float blockRedMax(float v, float* s) {
    v = warpRedMax(v);
    int lane = threadIdx.x & 31, w = threadIdx.x >> 5;
    if (lane == 0) s[w] = v;
    __syncthreads();
    if (threadIdx.x < 32) {
        float x = (threadIdx.x < 8) ? s[threadIdx.x] : -INFINITY;
        x = warpRedMax(x);
        if (threadIdx.x == 0) s[8] = x;
    }
    __syncthreads();
    float r = s[8];
    __syncthreads();
    return r;
}

__device__ __forceinline__ float4 ld4(const float* p) {
    return __ldcg(reinterpret_cast<const float4*>(p));
}

// =================================================================
// 64x64 GEMM tile, f32x2 FMA, float-A smem + in-loop dup,
// double-buffered smem stages (one __syncthreads per k-iter).
// tile -> bn = (tile%nx)*64, bm = ((tile/nx)&3)*64, z = tile/(nx*4)
// =================================================================
template<bool BTRANS>
__device__ void gemm_tile(Smem* sm, const float* __restrict__ A,
                          const float* __restrict__ B, float* __restrict__ Cp,
                          int tile, int nx, int Kc, int N, int Ktot, int cstride)
{
    const int tid = threadIdx.x;
    const int bn = (tile % nx) * 64;
    const int bm = ((tile / nx) & 3) * 64;
    const int kbase = (tile / (nx * 4)) * Kc;
    const int tx = tid & 15, ty = tid >> 4;
    const int ar = tid >> 2, ac4 = (tid & 3) << 2;
    const int br = tid >> 4, bc4 = (tid & 15) << 2;
    u64 acc[4][2] = {};
    const int niter = Kc >> 4;

    auto loadA = [&](int k0) -> float4 {
        return ld4(&A[(size_t)(bm + ar) * Ktot + kbase + k0 + ac4]);
    };
    auto loadB = [&](int k0) -> float4 {
        if (!BTRANS) return ld4(&B[(size_t)(kbase + k0 + br) * N + bn + bc4]);
        else         return ld4(&B[(size_t)(bn + ar) * Ktot + kbase + k0 + ac4]);
    };
    auto storeA = [&](int s, float4 v) {
        sm->A[s][ac4+0][ar] = v.x; sm->A[s][ac4+1][ar] = v.y;
        sm->A[s][ac4+2][ar] = v.z; sm->A[s][ac4+3][ar] = v.w;
    };
    auto storeB = [&](int s, float4 v) {
        if (!BTRANS) {
            *reinterpret_cast<float4*>(&sm->B1[s][br][bc4]) = v;
        } else {
            sm->B1[s][ac4+0][ar] = v.x; sm->B1[s][ac4+1][ar] = v.y;
            sm->B1[s][ac4+2][ar] = v.z; sm->B1[s][ac4+3][ar] = v.w;
        }
    };

    __syncthreads();   // protect smem reuse across tiles/phases
    float4 pa = loadA(0), pb = loadB(0);
    storeA(0, pa); storeB(0, pb);

    for (int it = 0; it < niter; ++it) {
        __syncthreads();
        if (it + 1 < niter) { pa = loadA((it+1) << 4); pb = loadB((it+1) << 4); }
        const int s = it & 1;
        #pragma unroll
        for (int k = 0; k < 16; ++k) {
            float4 av = *reinterpret_cast<const float4*>(&sm->A[s][k][ty*4]);
            const u64* bp = reinterpret_cast<const u64*>(&sm->B1[s][k][tx*4]);
            u64 rb0 = bp[0], rb1 = bp[1];
            u64 a0 = dup2(av.x), a1 = dup2(av.y), a2 = dup2(av.z), a3 = dup2(av.w);
            ffma2(acc[0][0], a0, rb0); ffma2(acc[0][1], a0, rb1);
            ffma2(acc[1][0], a1, rb0); ffma2(acc[1][1], a1, rb1);
            ffma2(acc[2][0], a2, rb0); ffma2(acc[2][1], a2, rb1);
            ffma2(acc[3][0], a3, rb0); ffma2(acc[3][1], a3, rb1);
        }
        if (it + 1 < niter) { storeA((it+1) & 1, pa); storeB((it+1) & 1, pb); }
    }
    float* C = Cp + (size_t)(tile / (nx * 4)) * cstride;
    #pragma unroll
    for (int i = 0; i < 4; ++i) {
        int row = bm + ty*4 + i;
        float2 v0 = unpk(acc[i][0]), v1 = unpk(acc[i][1]);
        *reinterpret_cast<float4*>(&C[(size_t)row * N + bn + tx*4]) =
            make_float4(v0.x, v0.y, v1.x, v1.y);
    }
}

// ---------------- Z = relu(sum 8 Zp + a) ----------------
__device__ void zred_tile(int tile, const float* Zp, const float* a, float* Z) {
    int i4 = tile * 1024 + threadIdx.x * 4;
    float4 r = make_float4(0.f, 0.f, 0.f, 0.f);
    #pragma unroll
    for (int s = 0; s < 8; ++s) {
        float4 v = ld4(&Zp[(size_t)s * SS + i4]);
        r.x += v.x; r.y += v.y; r.z += v.z; r.w += v.w;
    }
    float4 bb = ld4(&a[i4 & (HH - 1)]);
    r.x = fmaxf(r.x + bb.x, 0.f); r.y = fmaxf(r.y + bb.y, 0.f);
    r.z = fmaxf(r.z + bb.z, 0.f); r.w = fmaxf(r.w + bb.w, 0.f);
    *reinterpret_cast<float4*>(&Z[i4]) = r;
}

// ---------------- P = inclusive cumsum_t(h): 32 cols/tile, 8 thr/col ----------------
__device__ void prefix_tile(int p, const float* __restrict__ h, float* __restrict__ P) {
    const int q = p * 32 + (threadIdx.x >> 3);
    const int seg = threadIdx.x & 7;
    const int t0 = seg * 32;
    float v[32];
    #pragma unroll
    for (int i = 0; i < 32; ++i) v[i] = __ldcg(&h[(size_t)(t0 + i) * HH + q]);
    #pragma unroll
    for (int i = 1; i < 32; ++i) v[i] += v[i-1];
    float run = v[31];
    #pragma unroll
    for (int d = 1; d < 8; d <<= 1) {
        float n = __shfl_up_sync(0xffffffffu, run, d);
        if (seg >= d) run += n;
    }
    float off = run - v[31];
    #pragma unroll
    for (int i = 0; i < 32; ++i) P[(size_t)(t0 + i) * HH + q] = v[i] + off;
}

// ---------------- rows: Y reduce, LN fwd, softmax grad, LN bwd ----------------
__device__ void rows_tile(Smem* sm, int t,
    const float* __restrict__ Yp, const float* __restrict__ h,
    const float* __restrict__ bvec, const float* __restrict__ gamma,
    const float* __restrict__ beta, const int* __restrict__ targets,
    const float* __restrict__ Z, float* __restrict__ Y, float* __restrict__ D,
    float* __restrict__ HZ, float* __restrict__ cvec)
{
    const int q0 = threadIdx.x, q1 = threadIdx.x + 256;
    const int tgt = targets[t];
    const size_t i0 = (size_t)t*HH + q0, i1 = (size_t)t*HH + q1;

    float u0 = bvec[q0], u1 = bvec[q1];
    #pragma unroll
    for (int s = 0; s < 8; ++s) {
        u0 += __ldcg(&Yp[(size_t)s*SS + i0]);
        u1 += __ldcg(&Yp[(size_t)s*SS + i1]);
    }
    float h0 = h[i0], h1 = h[i1];
    float z0 = __ldcg(&Z[i0]), z1 = __ldcg(&Z[i1]);

    Y[i0] = u0; Y[i1] = u1;
    HZ[i0] = h0 * z0; HZ[i1] = h1 * z1;

    float sum_u = blockRedSum(u0 + u1, sm->red);
    float sum_h = blockRedSum(h0 + h1, sm->red);
    float m = sum_u * (1.f / HH);
    float du0 = u0 - m, du1 = u1 - m;
    float v = blockRedSum(du0*du0 + du1*du1, sm->red) * (1.f / HH);
    float rstd = rsqrtf(v + EPSV);
    float x0 = du0 * rstd, x1 = du1 * rstd;
    float g0 = gamma[q0], g1 = gamma[q1];
    float y0 = x0 * g0 + beta[q0];
    float y1 = x1 * g1 + beta[q1];

    float mx = blockRedMax(fmaxf(y0, y1), sm->red);
    float e0 = __expf(y0 - mx), e1 = __expf(y1 - mx);
    float se = blockRedSum(e0 + e1, sm->red);
    float inv_se = 1.f / se;
    float s0 = e0 * inv_se - (q0 == tgt ? 1.f : 0.f);
    float s1 = e1 * inv_se - (q1 == tgt ? 1.f : 0.f);
    float sg0 = s0 * g0, sg1 = s1 * g1;

    float msg  = blockRedSum(sg0 + sg1, sm->red) * (1.f / HH);
    float msgx = blockRedSum(sg0*x0 + sg1*x1, sm->red) * (1.f / HH);
    D[i0] = rstd * (sg0 - msg - x0 * msgx);
    D[i1] = rstd * (sg1 - msg - x1 * msgx);
    if (threadIdx.x == 0) cvec[t] = sum_h;
}

// ---------------- corr GEMM tile: A = tril_strict(sum 16 Bp + c[i]), dual B ----------------
__device__ void corr_tile(Smem* sm, int tile,
    const float* __restrict__ Bp, const float* __restrict__ cvec,
    const float* __restrict__ D, const float* __restrict__ P,
    float* __restrict__ C1p, float* __restrict__ C2p)
{
    const int tid = threadIdx.x;
    const int bn = (tile & 7) * 64;
    const int bm = ((tile >> 3) & 3) * 64;
    const int z  = tile >> 5;
    const int tx = tid & 15, ty = tid >> 4;
    const int ar = tid >> 2, ac4 = (tid & 3) << 2;
    const int br = tid >> 4, bc4 = (tid & 15) << 2;
    float* O1 = C1p + (size_t)z * SS;
    float* O2 = C2p + (size_t)z * SS;

    const int k_lo = z * 32;
    const bool active = k_lo < bm + 64;   // range is always exactly 32 when active

    if (!active) {
        float4 zz = make_float4(0.f, 0.f, 0.f, 0.f);
        #pragma unroll
        for (int i = 0; i < 4; ++i) {
            size_t idx = (size_t)(bm + ty*4 + i) * HH + bn + tx*4;
            *reinterpret_cast<float4*>(&O1[idx]) = zz;
            *reinterpret_cast<float4*>(&O2[idx]) = zz;
        }
        return;
    }

    auto loadA = [&](int k0) -> float4 {
        const int trow = bm + ar;
        size_t off = (size_t)trow * TT + k0 + ac4;
        float4 r = make_float4(0.f, 0.f, 0.f, 0.f);
        #pragma unroll
        for (int sl = 0; sl < 16; ++sl) {
            float4 v = ld4(&Bp[(size_t)sl * TSQ + off]);
            r.x += v.x; r.y += v.y; r.z += v.z; r.w += v.w;
        }
        float4 cc = ld4(&cvec[k0 + ac4]);
        r.x = (k0 + ac4 + 0 < trow) ? r.x + cc.x : 0.f;
        r.y = (k0 + ac4 + 1 < trow) ? r.y + cc.y : 0.f;
        r.z = (k0 + ac4 + 2 < trow) ? r.z + cc.z : 0.f;
        r.w = (k0 + ac4 + 3 < trow) ? r.w + cc.w : 0.f;
        return r;
    };
    auto storeA = [&](int s, float4 v) {
        sm->A[s][ac4+0][ar] = v.x; sm->A[s][ac4+1][ar] = v.y;
        sm->A[s][ac4+2][ar] = v.z; sm->A[s][ac4+3][ar] = v.w;
    };
    auto storeB = [&](int s, float4 d, float4 p) {
        *reinterpret_cast<float4*>(&sm->B1[s][br][bc4]) = d;
        *reinterpret_cast<float4*>(&sm->B2[s][br][bc4]) =
            make_float4(d.x*p.x, d.y*p.y, d.z*p.z, d.w*p.w);
    };

    __syncthreads();
    float4 pa = loadA(k_lo);
    float4 pd = ld4(&D[(size_t)(k_lo + br) * HH + bn + bc4]);
    float4 pp = ld4(&P[(size_t)(k_lo + br) * HH + bn + bc4]);
    storeA(0, pa); storeB(0, pd, pp);

    u64 acc1[4][2] = {}, acc2[4][2] = {};
    #pragma unroll
    for (int it = 0; it < 2; ++it) {
        __syncthreads();
        if (it == 0) {
            pa = loadA(k_lo + 16);
            pd = ld4(&D[(size_t)(k_lo + 16 + br) * HH + bn + bc4]);
            pp = ld4(&P[(size_t)(k_lo + 16 + br) * HH + bn + bc4]);
        }
        #pragma unroll
        for (int k = 0; k < 16; ++k) {
            float4 av = *reinterpret_cast<const float4*>(&sm->A[it][k][ty*4]);
            const u64* b1 = reinterpret_cast<const u64*>(&sm->B1[it][k][tx*4]);
            const u64* b2 = reinterpret_cast<const u64*>(&sm->B2[it][k][tx*4]);
            u64 r10 = b1[0], r11 = b1[1], r20 = b2[0], r21 = b2[1];
            u64 a0 = dup2(av.x), a1 = dup2(av.y), a2 = dup2(av.z), a3 = dup2(av.w);
            ffma2(acc1[0][0], a0, r10); ffma2(acc1[0][1], a0, r11);
            ffma2(acc2[0][0], a0, r20); ffma2(acc2[0][1], a0, r21);
            ffma2(acc1[1][0], a1, r10); ffma2(acc1[1][1], a1, r11);
            ffma2(acc2[1][0], a1, r20); ffma2(acc2[1][1], a1, r21);
            ffma2(acc1[2][0], a2, r10); ffma2(acc1[2][1], a2, r11);
            ffma2(acc2[2][0], a2, r20); ffma2(acc2[2][1], a2, r21);
            ffma2(acc1[3][0], a3, r10); ffma2(acc1[3][1], a3, r11);
            ffma2(acc2[3][0], a3, r20); ffma2(acc2[3][1], a3, r21);
        }
        if (it == 0) { storeA(1, pa); storeB(1, pd, pp); }
    }
    #pragma unroll
    for (int i = 0; i < 4; ++i) {
        size_t idx = (size_t)(bm + ty*4 + i) * HH + bn + tx*4;
        float2 u0 = unpk(acc1[i][0]), u1 = unpk(acc1[i][1]);
        float2 w0 = unpk(acc2[i][0]), w1 = unpk(acc2[i][1]);
        *reinterpret_cast<float4*>(&O1[idx]) = make_float4(u0.x, u0.y, u1.x, u1.y);
        *reinterpret_cast<float4*>(&O2[idx]) = make_float4(w0.x, w0.y, w1.x, w1.y);
    }
}

// ---------------- reduce corr partials + PRE + final LN ----------------
__device__ void ln_tile(Smem* sm, int t,
    const float* __restrict__ Y, const float* __restrict__ P,
    const float* __restrict__ C1p, const float* __restrict__ C2p,
    const float* __restrict__ gamma, const float* __restrict__ beta,
    float* __restrict__ out)
{
    const int q0 = threadIdx.x, q1 = threadIdx.x + 256;
    size_t i0 = (size_t)t*HH + q0, i1 = (size_t)t*HH + q1;

    float c1a = 0.f, c1b = 0.f, c2a = 0.f, c2b = 0.f;
    #pragma unroll
    for (int s = 0; s < 8; ++s) {
        c1a += __ldcg(&C1p[(size_t)s*SS + i0]);
        c1b += __ldcg(&C1p[(size_t)s*SS + i1]);
        c2a += __ldcg(&C2p[(size_t)s*SS + i0]);
        c2b += __ldcg(&C2p[(size_t)s*SS + i1]);
    }
    float u0 = __ldcg(&Y[i0]) - __ldcg(&P[i0]) * c1a + c2a;
    float u1 = __ldcg(&Y[i1]) - __ldcg(&P[i1]) * c1b + c2b;

    float m = blockRedSum(u0 + u1, sm->red) * (1.f / HH);
    float d0 = u0 - m, d1 = u1 - m;
    float v = blockRedSum(d0*d0 + d1*d1, sm->red) * (1.f / HH);
    float rstd = rsqrtf(v + EPSV);
    out[i0] = d0 * rstd * gamma[q0] + beta[q0];
    out[i1] = d1 * rstd * gamma[q1] + beta[q1];
}

// =================================================================
// mega kernel: 7 phases, 6 barriers, 296 persistent CTAs
// =================================================================
__global__ __launch_bounds__(256, 2) void mega_kernel(
    const float* __restrict__ h, const float* __restrict__ U,
    const float* __restrict__ W, const float* __restrict__ a,
    const float* __restrict__ b, const float* __restrict__ gamma,
    const float* __restrict__ beta, const int* __restrict__ tgts,
    float* __restrict__ out)
{
    __shared__ Smem sm;
    float* Zp  = g_part;                 // 8 slices SS (phase 1)
    float* Yp  = g_part + 8*(size_t)SS;  // 8 slices SS (phase 3)
    float* Bp  = g_part;                 // 16 slices TSQ (phase 5, reuses Zp)
    float* C1p = g_part + 16*(size_t)SS; // 8 slices SS
    float* C2p = g_part + 24*(size_t)SS; // 8 slices SS

    // Phase 1: Zp partials = h @ U (split-K 8, 256 tiles) + P prefix (16 tiles)
    for (int tile = blockIdx.x; tile < 272; tile += gridDim.x) {
        if (tile < 256) gemm_tile<false>(&sm, h, U, Zp, tile, 8, 64, HH, HH, SS);
        else            prefix_tile(tile - 256, h, g_P);
    }
    gbar();
    // Phase 2: Z = relu(sum Zp + a)
    for (int tile = blockIdx.x; tile < 128; tile += gridDim.x)
        zred_tile(tile, Zp, a, g_Z);
    gbar();
    // Phase 3: Yp partials = Z @ W (split-K 8, 256 tiles)
    for (int tile = blockIdx.x; tile < 256; tile += gridDim.x)
        gemm_tile<false>(&sm, g_Z, W, Yp, tile, 8, 64, HH, HH, SS);
    gbar();
    // Phase 4: rows -> Y, D, HZ, c
    for (int t = blockIdx.x; t < TT; t += gridDim.x)
        rows_tile(&sm, t, Yp, h, b, gamma, beta, tgts, g_Z, g_Y, g_D, g_HZ, g_c);
    gbar();
    // Phase 5: Bp partials = Z @ HZ^T (split-K 16, Kc=32, 256 tiles)
    for (int tile = blockIdx.x; tile < 256; tile += gridDim.x)
        gemm_tile<true>(&sm, g_Z, g_HZ, Bp, tile, 4, 32, TT, HH, TSQ);
    gbar();
    // Phase 6: C1p/C2p partials = tril_strict(sum Bp + c) @ {D, P*D} (split-K 8)
    for (int tile = blockIdx.x; tile < 256; tile += gridDim.x)
        corr_tile(&sm, tile, Bp, g_c, g_D, g_P, C1p, C2p);
    gbar();
    // Phase 7: out = LN(Y - P*C1 + C2)
    for (int t = blockIdx.x; t < TT; t += gridDim.x)
        ln_tile(&sm, t, g_Y, g_P, C1p, C2p, gamma, beta, out);
}

// ---------------- launch ----------------
extern "C" void kernel_launch(void* const* d_in, const int* in_sizes, int n_in,
                              void* d_out, int out_size)
{
    const float* h     = (const float*)d_in[0];
    const float* U     = (const float*)d_in[1];
    const float* W     = (const float*)d_in[2];
    const float* a     = (const float*)d_in[3];
    const float* b     = (const float*)d_in[4];
    const float* gamma = (const float*)d_in[5];
    const float* beta  = (const float*)d_in[6];
    const int*   tgts  = (const int*)d_in[7];
    float* out = (float*)d_out;

    mega_kernel<<<NCTA, 256>>>(h, U, W, a, b, gamma, beta, tgts, out);
}